// round 3
// baseline (speedup 1.0000x reference)
#include <cuda_runtime.h>

#define NNODES 50000
#define INDIM  256
#define HEADS1 4
#define CH1    32
#define D1     128      // HEADS1*CH1
#define OUTC   40

// ---------------- scratch (static device globals; no allocation) ----------------
__device__ float g_h1  [NNODES * D1];     // x @ W1 (raw, pre-normalization)
__device__ float g_out1[NNODES * D1];     // layer1 weighted aggregation
__device__ float g_als1[NNODES * HEADS1];
__device__ float g_ald1[NNODES * HEADS1];
__device__ float g_s1  [NNODES * HEADS1];
__device__ float g_h2  [NNODES * OUTC];
__device__ float g_als2[NNODES];
__device__ float g_ald2[NNODES];
__device__ float g_s2  [NNODES];

// ---------------- helpers ----------------
__device__ __forceinline__ void redAdd4(float4* addr, float4 v) {
    asm volatile("red.global.add.v4.f32 [%0], {%1,%2,%3,%4};"
                 :: "l"(addr), "f"(v.x), "f"(v.y), "f"(v.z), "f"(v.w) : "memory");
}

__device__ __forceinline__ float lrelu(float x) { return x > 0.f ? x : 0.2f * x; }

__device__ __forceinline__ unsigned f2tf(float f) {
    unsigned r;
    asm("cvt.rna.tf32.f32 %0, %1;" : "=r"(r) : "f"(f));
    return r;
}

__device__ __forceinline__ void mma_tf32(float c[4], const unsigned a[4], const unsigned b[2]) {
    asm volatile("mma.sync.aligned.m16n8k8.row.col.f32.tf32.tf32.f32 "
                 "{%0,%1,%2,%3}, {%4,%5,%6,%7}, {%8,%9}, {%0,%1,%2,%3};"
                 : "+f"(c[0]), "+f"(c[1]), "+f"(c[2]), "+f"(c[3])
                 : "r"(a[0]), "r"(a[1]), "r"(a[2]), "r"(a[3]), "r"(b[0]), "r"(b[1]));
}

// ---------------- init ----------------
__global__ __launch_bounds__(256) void k_init(float* dout, int n) {
    int i = blockIdx.x * blockDim.x + threadIdx.x;
    if (i < n * D1)     g_out1[i] = 0.f;
    if (i < n * OUTC)   dout[i]   = 0.f;
    if (i < n * HEADS1) g_s1[i]   = 0.f;
    if (i < n)          g_s2[i]   = 0.f;
}

// ---------------- GEMM1 (tf32 tensor cores): h1 = x @ W1  [N,256]x[256,128] --------
// BM=128, BN=128, BK=32. 8 warps in 4x2; warp tile 32x64 (2 m-frags x 8 n-frags).
__global__ __launch_bounds__(256) void k_gemm1(const float* __restrict__ x,
                                               const float* __restrict__ W1, int n) {
    __shared__ unsigned As[128][36];   // [m][k], pad->conflict-free frag loads
    __shared__ unsigned Bt[128][36];   // [n][k] (W1 transposed)
    int tid  = threadIdx.x;
    int lane = tid & 31;
    int wid  = tid >> 5;
    int wm   = wid & 3;          // warp row (x32)
    int wn   = wid >> 2;         // warp col (x64)
    int rowBase = blockIdx.x * 128;

    float acc[2][8][4];
#pragma unroll
    for (int mi = 0; mi < 2; mi++)
#pragma unroll
        for (int ni = 0; ni < 8; ni++)
#pragma unroll
            for (int j = 0; j < 4; j++) acc[mi][ni][j] = 0.f;

    for (int k0 = 0; k0 < INDIM; k0 += 32) {
        // stage A: 128x32 floats = 1024 float4, 4 per thread
#pragma unroll
        for (int t = 0; t < 4; t++) {
            int f = tid + t * 256;
            int r = f >> 3, c4 = f & 7;
            int gr = rowBase + r;
            float4 v = (gr < n) ? ((const float4*)x)[gr * (INDIM/4) + (k0 >> 2) + c4]
                                : make_float4(0.f, 0.f, 0.f, 0.f);
            uint4 u = make_uint4(f2tf(v.x), f2tf(v.y), f2tf(v.z), f2tf(v.w));
            *(uint4*)&As[r][c4 * 4] = u;
        }
        // stage B transposed: W1[k0+k][nn] -> Bt[nn][k], 4096 scalars, 16 per thread
#pragma unroll
        for (int t = 0; t < 16; t++) {
            int e = tid + t * 256;
            int k = e >> 7, nn = e & 127;
            Bt[nn][k] = f2tf(W1[(k0 + k) * D1 + nn]);
        }
        __syncthreads();
#pragma unroll
        for (int k8 = 0; k8 < 4; k8++) {
            int kb = k8 * 8;
            unsigned a[2][4], b[8][2];
#pragma unroll
            for (int mi = 0; mi < 2; mi++) {
                int r = wm * 32 + mi * 16 + (lane >> 2);
                a[mi][0] = As[r][kb + (lane & 3)];
                a[mi][1] = As[r + 8][kb + (lane & 3)];
                a[mi][2] = As[r][kb + (lane & 3) + 4];
                a[mi][3] = As[r + 8][kb + (lane & 3) + 4];
            }
#pragma unroll
            for (int ni = 0; ni < 8; ni++) {
                int c = wn * 64 + ni * 8 + (lane >> 2);
                b[ni][0] = Bt[c][kb + (lane & 3)];
                b[ni][1] = Bt[c][kb + (lane & 3) + 4];
            }
#pragma unroll
            for (int mi = 0; mi < 2; mi++)
#pragma unroll
                for (int ni = 0; ni < 8; ni++)
                    mma_tf32(acc[mi][ni], a[mi], b[ni]);
        }
        __syncthreads();
    }
    // epilogue: write h1
#pragma unroll
    for (int mi = 0; mi < 2; mi++) {
        int r = rowBase + wm * 32 + mi * 16 + (lane >> 2);
#pragma unroll
        for (int ni = 0; ni < 8; ni++) {
            int c = wn * 64 + ni * 8 + 2 * (lane & 3);
            if (r < n)
                *(float2*)&g_h1[r * D1 + c] = make_float2(acc[mi][ni][0], acc[mi][ni][1]);
            if (r + 8 < n)
                *(float2*)&g_h1[(r + 8) * D1 + c] = make_float2(acc[mi][ni][2], acc[mi][ni][3]);
        }
    }
}

// ---------------- attention logits, layer 1 ----------------
__global__ __launch_bounds__(256) void k_al1(const float* __restrict__ a_src,
                                             const float* __restrict__ a_dst, int n) {
    int nid = blockIdx.x * blockDim.x + threadIdx.x;
    if (nid >= n) return;
    const float4* row = (const float4*)(g_h1 + nid * D1);
#pragma unroll
    for (int hd = 0; hd < HEADS1; hd++) {
        float s = 0.f, d = 0.f;
#pragma unroll
        for (int c4 = 0; c4 < 8; c4++) {
            float4 v  = row[hd * 8 + c4];
            float4 as = ((const float4*)a_src)[hd * 8 + c4];
            float4 ad = ((const float4*)a_dst)[hd * 8 + c4];
            s += v.x*as.x + v.y*as.y + v.z*as.z + v.w*as.w;
            d += v.x*ad.x + v.y*ad.y + v.z*ad.z + v.w*ad.w;
        }
        g_als1[nid * HEADS1 + hd] = s;
        g_ald1[nid * HEADS1 + hd] = d;
    }
}

// ---------------- edge accumulate, layer 1 (warp per edge) ----------------
__global__ __launch_bounds__(256) void k_eacc1(const int* __restrict__ ei, int E, int ET) {
    int gtid = blockIdx.x * blockDim.x + threadIdx.x;
    int w = gtid >> 5;
    int l = gtid & 31;
    if (w >= ET) return;
    int src, dst;
    if (w < E) { src = __ldg(&ei[w]); dst = __ldg(&ei[E + w]); }
    else       { src = dst = w - E; }
    int hd = l >> 3;
    float e = lrelu(g_als1[src * 4 + hd] + g_ald1[dst * 4 + hd]);
    float p = __expf(e);
    if ((l & 7) == 0) atomicAdd(&g_s1[dst * 4 + hd], p);
    float4 v = ((const float4*)g_h1)[src * 32 + l];
    redAdd4(((float4*)g_out1) + dst * 32 + l,
            make_float4(v.x * p, v.y * p, v.z * p, v.w * p));
}

// ---------------- GEMM2 (tf32, finalize-on-load): h2 = elu(out1/s1+b1) @ W2 ------
// [N,128]x[128,40]. BM=128, BK=32 (== one head per K-tile), 8 warps of 16 rows,
// each warp covers all 40 cols (5 n-frags).
__global__ __launch_bounds__(256) void k_gemm2(const float* __restrict__ W2,
                                               const float* __restrict__ b1, int n) {
    __shared__ unsigned As[128][36];
    __shared__ unsigned Bt[OUTC][132];   // whole W2 transposed: [n][k]
    int tid  = threadIdx.x;
    int lane = tid & 31;
    int wid  = tid >> 5;
    int rowBase = blockIdx.x * 128;

    // stage whole W2 (128x40) once
    for (int e = tid; e < D1 * OUTC; e += 256) {
        int k = e / OUTC, nn = e - k * OUTC;
        Bt[nn][k] = f2tf(W2[k * OUTC + nn]);
    }

    float acc[5][4];
#pragma unroll
    for (int ni = 0; ni < 5; ni++)
#pragma unroll
        for (int j = 0; j < 4; j++) acc[ni][j] = 0.f;

    for (int kt = 0; kt < 4; kt++) {       // K-tile == head
        // stage A with fused finalize: elu(out1/s1 + b1)
        __syncthreads();
#pragma unroll
        for (int t = 0; t < 4; t++) {
            int f = tid + t * 256;
            int r = f >> 3, c4 = f & 7;
            int gr = rowBase + r;
            float4 v = make_float4(0.f, 0.f, 0.f, 0.f);
            if (gr < n) {
                float inv = __fdividef(1.f, g_s1[gr * 4 + kt]);
                v = ((const float4*)g_out1)[gr * 32 + kt * 8 + c4];
                float4 b = ((const float4*)b1)[kt * 8 + c4];
                v.x = v.x * inv + b.x;  v.y = v.y * inv + b.y;
                v.z = v.z * inv + b.z;  v.w = v.w * inv + b.w;
                v.x = v.x > 0.f ? v.x : expm1f(v.x);
                v.y = v.y > 0.f ? v.y : expm1f(v.y);
                v.z = v.z > 0.f ? v.z : expm1f(v.z);
                v.w = v.w > 0.f ? v.w : expm1f(v.w);
            }
            uint4 u = make_uint4(f2tf(v.x), f2tf(v.y), f2tf(v.z), f2tf(v.w));
            *(uint4*)&As[r][c4 * 4] = u;
        }
        __syncthreads();
#pragma unroll
        for (int k8 = 0; k8 < 4; k8++) {
            int kb = k8 * 8;
            unsigned a[4], b[5][2];
            int r = wid * 16 + (lane >> 2);
            a[0] = As[r][kb + (lane & 3)];
            a[1] = As[r + 8][kb + (lane & 3)];
            a[2] = As[r][kb + (lane & 3) + 4];
            a[3] = As[r + 8][kb + (lane & 3) + 4];
#pragma unroll
            for (int ni = 0; ni < 5; ni++) {
                int c = ni * 8 + (lane >> 2);
                b[ni][0] = Bt[c][kt * 32 + kb + (lane & 3)];
                b[ni][1] = Bt[c][kt * 32 + kb + (lane & 3) + 4];
            }
#pragma unroll
            for (int ni = 0; ni < 5; ni++)
                mma_tf32(acc[ni], a, b[ni]);
        }
    }
    // epilogue: write h2 (no bias here; b2 added in fin2)
    int r = rowBase + wid * 16 + (lane >> 2);
#pragma unroll
    for (int ni = 0; ni < 5; ni++) {
        int c = ni * 8 + 2 * (lane & 3);
        if (r < n)
            *(float2*)&g_h2[r * OUTC + c] = make_float2(acc[ni][0], acc[ni][1]);
        if (r + 8 < n)
            *(float2*)&g_h2[(r + 8) * OUTC + c] = make_float2(acc[ni][2], acc[ni][3]);
    }
}

// ---------------- attention logits, layer 2 ----------------
__global__ __launch_bounds__(256) void k_al2(const float* __restrict__ a_src,
                                             const float* __restrict__ a_dst, int n) {
    int nid = blockIdx.x * blockDim.x + threadIdx.x;
    if (nid >= n) return;
    const float4* row = (const float4*)(g_h2 + nid * OUTC);
    float s = 0.f, d = 0.f;
#pragma unroll
    for (int c4 = 0; c4 < 10; c4++) {
        float4 v  = row[c4];
        float4 as = ((const float4*)a_src)[c4];
        float4 ad = ((const float4*)a_dst)[c4];
        s += v.x*as.x + v.y*as.y + v.z*as.z + v.w*as.w;
        d += v.x*ad.x + v.y*ad.y + v.z*ad.z + v.w*ad.w;
    }
    g_als2[nid] = s;
    g_ald2[nid] = d;
}

// ---------------- edge accumulate, layer 2 (10 float4 per edge) ----------------
__global__ __launch_bounds__(256) void k_eacc2(const int* __restrict__ ei, int E, int ET,
                                               float* __restrict__ out) {
    int idx = blockIdx.x * blockDim.x + threadIdx.x;
    if (idx >= ET * 10) return;
    int eidx = idx / 10;
    int c4   = idx - eidx * 10;
    int src, dst;
    if (eidx < E) { src = __ldg(&ei[eidx]); dst = __ldg(&ei[E + eidx]); }
    else          { src = dst = eidx - E; }
    float e = lrelu(g_als2[src] + g_ald2[dst]);
    float p = __expf(e);
    if (c4 == 0) atomicAdd(&g_s2[dst], p);
    float4 v = ((const float4*)g_h2)[src * 10 + c4];
    redAdd4(((float4*)out) + dst * 10 + c4,
            make_float4(v.x * p, v.y * p, v.z * p, v.w * p));
}

// ---------------- finalize layer 2: normalize + bias + log_softmax (warp/node) ---
__global__ __launch_bounds__(256) void k_fin2(float* __restrict__ out,
                                              const float* __restrict__ b2, int n) {
    int gtid = blockIdx.x * blockDim.x + threadIdx.x;
    int w = gtid >> 5;
    int l = gtid & 31;
    if (w >= n) return;
    float inv = 1.f / g_s2[w];
    float a = out[w * OUTC + l] * inv + b2[l];
    float b = (l < 8) ? out[w * OUTC + 32 + l] * inv + b2[32 + l]
                      : __int_as_float(0xff800000);
    float mx = fmaxf(a, b);
#pragma unroll
    for (int o = 16; o; o >>= 1) mx = fmaxf(mx, __shfl_xor_sync(0xffffffffu, mx, o));
    float se = __expf(a - mx) + ((l < 8) ? __expf(b - mx) : 0.f);
#pragma unroll
    for (int o = 16; o; o >>= 1) se += __shfl_xor_sync(0xffffffffu, se, o);
    float lse = logf(se);
    out[w * OUTC + l] = a - mx - lse;
    if (l < 8) out[w * OUTC + 32 + l] = b - mx - lse;
}

// ---------------- launch ----------------
static inline int cdiv(int a, int b) { return (a + b - 1) / b; }

extern "C" void kernel_launch(void* const* d_in, const int* in_sizes, int n_in,
                              void* d_out, int out_size) {
    const float* x      = (const float*)d_in[0];
    const int*   ei     = (const int*)  d_in[1];
    const float* W1     = (const float*)d_in[2];
    const float* a_src1 = (const float*)d_in[3];
    const float* a_dst1 = (const float*)d_in[4];
    const float* b1     = (const float*)d_in[5];
    const float* W2     = (const float*)d_in[6];
    const float* a_src2 = (const float*)d_in[7];
    const float* a_dst2 = (const float*)d_in[8];
    const float* b2     = (const float*)d_in[9];
    float* out = (float*)d_out;

    const int n  = NNODES;
    const int E  = in_sizes[1] / 2;
    const int ET = E + n;

    k_init <<<cdiv(n * D1, 256), 256>>>(out, n);
    k_gemm1<<<cdiv(n, 128), 256>>>(x, W1, n);
    k_al1  <<<cdiv(n, 256), 256>>>(a_src1, a_dst1, n);
    k_eacc1<<<cdiv(ET * 32, 256), 256>>>(ei, E, ET);
    k_gemm2<<<cdiv(n, 128), 256>>>(W2, b1, n);
    k_al2  <<<cdiv(n, 256), 256>>>(a_src2, a_dst2, n);
    k_eacc2<<<cdiv(ET * 10, 256), 256>>>(ei, E, ET, out);
    k_fin2 <<<cdiv(n * 32, 256), 256>>>(out, b2, n);
}

// round 4
// speedup vs baseline: 1.4641x; 1.4641x over previous
#include <cuda_runtime.h>

#define NNODES 50000
#define INDIM  256
#define HEADS1 4
#define CH1    32
#define D1     128      // HEADS1*CH1
#define OUTC   40
#define MAXE   800000
#define MAXET  (MAXE + NNODES)

// ---------------- scratch (static device globals; no allocation) ----------------
__device__ float g_h1  [NNODES * D1];     // x @ W1
__device__ float g_out1[NNODES * D1];     // layer1 aggregated (already / sum)
__device__ float g_als1[NNODES * HEADS1];
__device__ float g_ald1[NNODES * HEADS1];
__device__ float g_h2  [NNODES * OUTC];
__device__ float g_als2[NNODES];
__device__ float g_ald2[NNODES];
// CSR (dst-sorted) structure, built once per launch, shared by both layers
__device__ int g_deg    [NNODES];
__device__ int g_rowptr [NNODES + 1];
__device__ int g_cursor [NNODES];
__device__ int g_csrsrc [MAXET];

// ---------------- helpers ----------------
__device__ __forceinline__ float lrelu(float x) { return x > 0.f ? x : 0.2f * x; }

__device__ __forceinline__ unsigned f2tf(float f) {
    unsigned r;
    asm("cvt.rna.tf32.f32 %0, %1;" : "=r"(r) : "f"(f));
    return r;
}

__device__ __forceinline__ void mma_tf32(float c[4], const unsigned a[4], const unsigned b[2]) {
    asm volatile("mma.sync.aligned.m16n8k8.row.col.f32.tf32.tf32.f32 "
                 "{%0,%1,%2,%3}, {%4,%5,%6,%7}, {%8,%9}, {%0,%1,%2,%3};"
                 : "+f"(c[0]), "+f"(c[1]), "+f"(c[2]), "+f"(c[3])
                 : "r"(a[0]), "r"(a[1]), "r"(a[2]), "r"(a[3]), "r"(b[0]), "r"(b[1]));
}

// ---------------- CSR build ----------------
__global__ __launch_bounds__(256) void k_deg_init(int n) {
    int i = blockIdx.x * blockDim.x + threadIdx.x;
    if (i < n) g_deg[i] = 1;            // self-loop
}

__global__ __launch_bounds__(256) void k_deg_count(const int* __restrict__ ei, int E) {
    int i = blockIdx.x * blockDim.x + threadIdx.x;
    if (i < E) atomicAdd(&g_deg[ei[E + i]], 1);
}

#define SCAN_T 1024
#define SCAN_C 49   // ceil(50000/1024)
__global__ __launch_bounds__(SCAN_T) void k_scan(int n) {
    __shared__ int ss[SCAN_T];
    int t = threadIdx.x;
    int base = t * SCAN_C;
    int local = 0;
#pragma unroll
    for (int j = 0; j < SCAN_C; j++) {
        int idx = base + j;
        if (idx < n) local += g_deg[idx];
    }
    ss[t] = local;
    __syncthreads();
    for (int off = 1; off < SCAN_T; off <<= 1) {
        int v = (t >= off) ? ss[t - off] : 0;
        __syncthreads();
        ss[t] += v;
        __syncthreads();
    }
    int run = ss[t] - local;   // exclusive prefix
#pragma unroll
    for (int j = 0; j < SCAN_C; j++) {
        int idx = base + j;
        if (idx < n) {
            g_rowptr[idx] = run;
            g_cursor[idx] = run;
            run += g_deg[idx];
        }
    }
    if (t == SCAN_T - 1) g_rowptr[n] = ss[SCAN_T - 1];
}

__global__ __launch_bounds__(256) void k_scatter(const int* __restrict__ ei, int E, int ET) {
    int i = blockIdx.x * blockDim.x + threadIdx.x;
    if (i >= ET) return;
    int src, dst;
    if (i < E) { src = ei[i]; dst = ei[E + i]; }
    else       { src = dst = i - E; }
    int pos = atomicAdd(&g_cursor[dst], 1);
    g_csrsrc[pos] = src;
}

// ---------------- GEMM1 (tf32): h1 = x @ W1  [N,256]x[256,128] ----------------
__global__ __launch_bounds__(256) void k_gemm1(const float* __restrict__ x,
                                               const float* __restrict__ W1, int n) {
    __shared__ unsigned As[128][36];
    __shared__ unsigned Bt[128][36];
    int tid  = threadIdx.x;
    int lane = tid & 31;
    int wid  = tid >> 5;
    int wm   = wid & 3;
    int wn   = wid >> 2;
    int rowBase = blockIdx.x * 128;

    float acc[2][8][4];
#pragma unroll
    for (int mi = 0; mi < 2; mi++)
#pragma unroll
        for (int ni = 0; ni < 8; ni++)
#pragma unroll
            for (int j = 0; j < 4; j++) acc[mi][ni][j] = 0.f;

    for (int k0 = 0; k0 < INDIM; k0 += 32) {
#pragma unroll
        for (int t = 0; t < 4; t++) {
            int f = tid + t * 256;
            int r = f >> 3, c4 = f & 7;
            int gr = rowBase + r;
            float4 v = (gr < n) ? ((const float4*)x)[gr * (INDIM/4) + (k0 >> 2) + c4]
                                : make_float4(0.f, 0.f, 0.f, 0.f);
            uint4 u = make_uint4(f2tf(v.x), f2tf(v.y), f2tf(v.z), f2tf(v.w));
            *(uint4*)&As[r][c4 * 4] = u;
        }
#pragma unroll
        for (int t = 0; t < 16; t++) {
            int e = tid + t * 256;
            int k = e >> 7, nn = e & 127;
            Bt[nn][k] = f2tf(W1[(k0 + k) * D1 + nn]);
        }
        __syncthreads();
#pragma unroll
        for (int k8 = 0; k8 < 4; k8++) {
            int kb = k8 * 8;
            unsigned a[2][4], b[8][2];
#pragma unroll
            for (int mi = 0; mi < 2; mi++) {
                int r = wm * 32 + mi * 16 + (lane >> 2);
                a[mi][0] = As[r][kb + (lane & 3)];
                a[mi][1] = As[r + 8][kb + (lane & 3)];
                a[mi][2] = As[r][kb + (lane & 3) + 4];
                a[mi][3] = As[r + 8][kb + (lane & 3) + 4];
            }
#pragma unroll
            for (int ni = 0; ni < 8; ni++) {
                int c = wn * 64 + ni * 8 + (lane >> 2);
                b[ni][0] = Bt[c][kb + (lane & 3)];
                b[ni][1] = Bt[c][kb + (lane & 3) + 4];
            }
#pragma unroll
            for (int mi = 0; mi < 2; mi++)
#pragma unroll
                for (int ni = 0; ni < 8; ni++)
                    mma_tf32(acc[mi][ni], a[mi], b[ni]);
        }
        __syncthreads();
    }
#pragma unroll
    for (int mi = 0; mi < 2; mi++) {
        int r = rowBase + wm * 32 + mi * 16 + (lane >> 2);
#pragma unroll
        for (int ni = 0; ni < 8; ni++) {
            int c = wn * 64 + ni * 8 + 2 * (lane & 3);
            if (r < n)
                *(float2*)&g_h1[r * D1 + c] = make_float2(acc[mi][ni][0], acc[mi][ni][1]);
            if (r + 8 < n)
                *(float2*)&g_h1[(r + 8) * D1 + c] = make_float2(acc[mi][ni][2], acc[mi][ni][3]);
        }
    }
}

// ---------------- attention logits, layer 1 ----------------
__global__ __launch_bounds__(256) void k_al1(const float* __restrict__ a_src,
                                             const float* __restrict__ a_dst, int n) {
    int nid = blockIdx.x * blockDim.x + threadIdx.x;
    if (nid >= n) return;
    const float4* row = (const float4*)(g_h1 + nid * D1);
#pragma unroll
    for (int hd = 0; hd < HEADS1; hd++) {
        float s = 0.f, d = 0.f;
#pragma unroll
        for (int c4 = 0; c4 < 8; c4++) {
            float4 v  = row[hd * 8 + c4];
            float4 as = ((const float4*)a_src)[hd * 8 + c4];
            float4 ad = ((const float4*)a_dst)[hd * 8 + c4];
            s += v.x*as.x + v.y*as.y + v.z*as.z + v.w*as.w;
            d += v.x*ad.x + v.y*ad.y + v.z*ad.z + v.w*ad.w;
        }
        g_als1[nid * HEADS1 + hd] = s;
        g_ald1[nid * HEADS1 + hd] = d;
    }
}

// ---------------- layer-1 aggregation: warp per dst node (gather, no atomics) ----
// lane l covers channels [4l, 4l+3], head = l>>3. out = (sum p*h)/(sum p).
__global__ __launch_bounds__(256) void k_agg1(int n) {
    int node = blockIdx.x * 8 + (threadIdx.x >> 5);
    if (node >= n) return;
    int l = threadIdx.x & 31;
    int beg = g_rowptr[node], end = g_rowptr[node + 1];
    float4 d4 = *((const float4*)g_ald1 + node);
    float dlo = (l & 8) ? d4.y : d4.x;
    float dhi = (l & 8) ? d4.w : d4.z;
    float dv  = (l & 16) ? dhi : dlo;
    float ax = 0.f, ay = 0.f, az = 0.f, aw = 0.f, psum = 0.f;
    for (int e = beg; e < end; e++) {
        int src = __ldg(&g_csrsrc[e]);
        float4 s4 = __ldg((const float4*)g_als1 + src);
        float slo = (l & 8) ? s4.y : s4.x;
        float shi = (l & 8) ? s4.w : s4.z;
        float sv  = (l & 16) ? shi : slo;
        float p = __expf(lrelu(sv + dv));
        float4 h = __ldg((const float4*)g_h1 + src * 32 + l);
        ax += p * h.x; ay += p * h.y; az += p * h.z; aw += p * h.w;
        psum += p;
    }
    float inv = __fdividef(1.f, psum);
    ((float4*)g_out1)[node * 32 + l] = make_float4(ax * inv, ay * inv, az * inv, aw * inv);
}

// ---------------- GEMM2 (tf32): h2 = elu(out1 + b1) @ W2  [N,128]x[128,40] -------
__global__ __launch_bounds__(256) void k_gemm2(const float* __restrict__ W2,
                                               const float* __restrict__ b1, int n) {
    __shared__ unsigned As[128][36];
    __shared__ unsigned Bt[OUTC][132];
    int tid  = threadIdx.x;
    int lane = tid & 31;
    int wid  = tid >> 5;
    int rowBase = blockIdx.x * 128;

    for (int e = tid; e < D1 * OUTC; e += 256) {
        int k = e / OUTC, nn = e - k * OUTC;
        Bt[nn][k] = f2tf(W2[k * OUTC + nn]);
    }

    float acc[5][4];
#pragma unroll
    for (int ni = 0; ni < 5; ni++)
#pragma unroll
        for (int j = 0; j < 4; j++) acc[ni][j] = 0.f;

    for (int kt = 0; kt < 4; kt++) {
        __syncthreads();
#pragma unroll
        for (int t = 0; t < 4; t++) {
            int f = tid + t * 256;
            int r = f >> 3, c4 = f & 7;
            int gr = rowBase + r;
            float4 v = make_float4(0.f, 0.f, 0.f, 0.f);
            if (gr < n) {
                v = ((const float4*)g_out1)[gr * 32 + kt * 8 + c4];
                float4 b = ((const float4*)b1)[kt * 8 + c4];
                v.x += b.x;  v.y += b.y;  v.z += b.z;  v.w += b.w;
                v.x = v.x > 0.f ? v.x : expm1f(v.x);
                v.y = v.y > 0.f ? v.y : expm1f(v.y);
                v.z = v.z > 0.f ? v.z : expm1f(v.z);
                v.w = v.w > 0.f ? v.w : expm1f(v.w);
            }
            uint4 u = make_uint4(f2tf(v.x), f2tf(v.y), f2tf(v.z), f2tf(v.w));
            *(uint4*)&As[r][c4 * 4] = u;
        }
        __syncthreads();
#pragma unroll
        for (int k8 = 0; k8 < 4; k8++) {
            int kb = k8 * 8;
            unsigned a[4], b[5][2];
            int r = wid * 16 + (lane >> 2);
            a[0] = As[r][kb + (lane & 3)];
            a[1] = As[r + 8][kb + (lane & 3)];
            a[2] = As[r][kb + (lane & 3) + 4];
            a[3] = As[r + 8][kb + (lane & 3) + 4];
#pragma unroll
            for (int ni = 0; ni < 5; ni++) {
                int c = ni * 8 + (lane >> 2);
                b[ni][0] = Bt[c][kt * 32 + kb + (lane & 3)];
                b[ni][1] = Bt[c][kt * 32 + kb + (lane & 3) + 4];
            }
#pragma unroll
            for (int ni = 0; ni < 5; ni++)
                mma_tf32(acc[ni], a, b[ni]);
        }
    }
    int r = rowBase + wid * 16 + (lane >> 2);
#pragma unroll
    for (int ni = 0; ni < 5; ni++) {
        int c = ni * 8 + 2 * (lane & 3);
        if (r < n)
            *(float2*)&g_h2[r * OUTC + c] = make_float2(acc[ni][0], acc[ni][1]);
        if (r + 8 < n)
            *(float2*)&g_h2[(r + 8) * OUTC + c] = make_float2(acc[ni][2], acc[ni][3]);
    }
}

// ---------------- attention logits, layer 2 ----------------
__global__ __launch_bounds__(256) void k_al2(const float* __restrict__ a_src,
                                             const float* __restrict__ a_dst, int n) {
    int nid = blockIdx.x * blockDim.x + threadIdx.x;
    if (nid >= n) return;
    const float4* row = (const float4*)(g_h2 + nid * OUTC);
    float s = 0.f, d = 0.f;
#pragma unroll
    for (int c4 = 0; c4 < 10; c4++) {
        float4 v  = row[c4];
        float4 as = ((const float4*)a_src)[c4];
        float4 ad = ((const float4*)a_dst)[c4];
        s += v.x*as.x + v.y*as.y + v.z*as.z + v.w*as.w;
        d += v.x*ad.x + v.y*ad.y + v.z*ad.z + v.w*ad.w;
    }
    g_als2[nid] = s;
    g_ald2[nid] = d;
}

// ---------------- layer-2 aggregation: warp per dst node ----------------
// lane l covers channel l, lanes 0-7 also cover channel 32+l. Writes d_out directly.
__global__ __launch_bounds__(256) void k_agg2(float* __restrict__ out, int n) {
    int node = blockIdx.x * 8 + (threadIdx.x >> 5);
    if (node >= n) return;
    int l = threadIdx.x & 31;
    int beg = g_rowptr[node], end = g_rowptr[node + 1];
    float dv = g_ald2[node];
    float aa = 0.f, ab = 0.f, psum = 0.f;
    for (int e = beg; e < end; e++) {
        int src = __ldg(&g_csrsrc[e]);
        float sv = __ldg(&g_als2[src]);
        float p = __expf(lrelu(sv + dv));
        aa += p * __ldg(&g_h2[src * OUTC + l]);
        if (l < 8) ab += p * __ldg(&g_h2[src * OUTC + 32 + l]);
        psum += p;
    }
    float inv = __fdividef(1.f, psum);
    out[node * OUTC + l] = aa * inv;
    if (l < 8) out[node * OUTC + 32 + l] = ab * inv;
}

// ---------------- finalize: bias + log_softmax (warp/node, in place) ----------------
__global__ __launch_bounds__(256) void k_fin2(float* __restrict__ out,
                                              const float* __restrict__ b2, int n) {
    int gtid = blockIdx.x * blockDim.x + threadIdx.x;
    int w = gtid >> 5;
    int l = gtid & 31;
    if (w >= n) return;
    float a = out[w * OUTC + l] + b2[l];
    float b = (l < 8) ? out[w * OUTC + 32 + l] + b2[32 + l]
                      : __int_as_float(0xff800000);
    float mx = fmaxf(a, b);
#pragma unroll
    for (int o = 16; o; o >>= 1) mx = fmaxf(mx, __shfl_xor_sync(0xffffffffu, mx, o));
    float se = __expf(a - mx) + ((l < 8) ? __expf(b - mx) : 0.f);
#pragma unroll
    for (int o = 16; o; o >>= 1) se += __shfl_xor_sync(0xffffffffu, se, o);
    float lse = logf(se);
    out[w * OUTC + l] = a - mx - lse;
    if (l < 8) out[w * OUTC + 32 + l] = b - mx - lse;
}

// ---------------- launch ----------------
static inline int cdiv(int a, int b) { return (a + b - 1) / b; }

extern "C" void kernel_launch(void* const* d_in, const int* in_sizes, int n_in,
                              void* d_out, int out_size) {
    const float* x      = (const float*)d_in[0];
    const int*   ei     = (const int*)  d_in[1];
    const float* W1     = (const float*)d_in[2];
    const float* a_src1 = (const float*)d_in[3];
    const float* a_dst1 = (const float*)d_in[4];
    const float* b1     = (const float*)d_in[5];
    const float* W2     = (const float*)d_in[6];
    const float* a_src2 = (const float*)d_in[7];
    const float* a_dst2 = (const float*)d_in[8];
    const float* b2     = (const float*)d_in[9];
    float* out = (float*)d_out;

    const int n  = NNODES;
    const int E  = in_sizes[1] / 2;
    const int ET = E + n;

    // CSR build (overlaps conceptually with gemm1 work in the same stream order)
    k_deg_init <<<cdiv(n, 256), 256>>>(n);
    k_deg_count<<<cdiv(E, 256), 256>>>(ei, E);
    k_scan     <<<1, SCAN_T>>>(n);
    k_scatter  <<<cdiv(ET, 256), 256>>>(ei, E, ET);

    k_gemm1<<<cdiv(n, 128), 256>>>(x, W1, n);
    k_al1  <<<cdiv(n, 256), 256>>>(a_src1, a_dst1, n);
    k_agg1 <<<cdiv(n, 8), 256>>>(n);
    k_gemm2<<<cdiv(n, 128), 256>>>(W2, b1, n);
    k_al2  <<<cdiv(n, 256), 256>>>(a_src2, a_dst2, n);
    k_agg2 <<<cdiv(n, 8), 256>>>(out, n);
    k_fin2 <<<cdiv(n, 8), 256>>>(out, b2, n);
}

// round 5
// speedup vs baseline: 1.6261x; 1.1106x over previous
#include <cuda_runtime.h>
#include <cuda_fp16.h>

#define NNODES 50000
#define INDIM  256
#define HEADS1 4
#define CH1    32
#define D1     128      // HEADS1*CH1
#define OUTC   40
#define MAXE   800000
#define MAXET  (MAXE + NNODES)

// ---------------- scratch (static device globals; no allocation) ----------------
__device__ __half g_h1h [NNODES * D1];    // x @ W1, fp16 (gather payload)
__device__ float  g_out1[NNODES * D1];    // layer1 aggregated (already / sum)
__device__ float  g_als1[NNODES * HEADS1];
__device__ float  g_ald1[NNODES * HEADS1];
__device__ __half g_h2h [NNODES * OUTC];  // layer2 pre-agg features, fp16
__device__ float  g_als2[NNODES];
__device__ float  g_ald2[NNODES];
// CSR (dst-sorted), built once per launch, shared by both layers
__device__ int g_deg    [NNODES];
__device__ int g_rowptr [NNODES + 1];
__device__ int g_cursor [NNODES];
__device__ int g_csrsrc [MAXET];

// ---------------- helpers ----------------
__device__ __forceinline__ float lrelu(float x) { return x > 0.f ? x : 0.2f * x; }

__device__ __forceinline__ unsigned f2tf(float f) {
    unsigned r;
    asm("cvt.rna.tf32.f32 %0, %1;" : "=r"(r) : "f"(f));
    return r;
}

__device__ __forceinline__ void mma_tf32(float c[4], const unsigned a[4], const unsigned b[2]) {
    asm volatile("mma.sync.aligned.m16n8k8.row.col.f32.tf32.tf32.f32 "
                 "{%0,%1,%2,%3}, {%4,%5,%6,%7}, {%8,%9}, {%0,%1,%2,%3};"
                 : "+f"(c[0]), "+f"(c[1]), "+f"(c[2]), "+f"(c[3])
                 : "r"(a[0]), "r"(a[1]), "r"(a[2]), "r"(a[3]), "r"(b[0]), "r"(b[1]));
}

// pick head component (head = l>>3) from float4 of per-head logits
__device__ __forceinline__ float pick4(float4 q, int l) {
    float lo = (l & 8)  ? q.y : q.x;
    float hi = (l & 8)  ? q.w : q.z;
    return    (l & 16) ? hi : lo;
}

// ---------------- CSR build ----------------
__global__ __launch_bounds__(256) void k_deg_init(int n) {
    int i = blockIdx.x * blockDim.x + threadIdx.x;
    if (i < n) g_deg[i] = 1;            // self-loop
}

__global__ __launch_bounds__(256) void k_deg_count(const int* __restrict__ ei, int E) {
    int i = blockIdx.x * blockDim.x + threadIdx.x;
    if (i < E) atomicAdd(&g_deg[ei[E + i]], 1);
}

#define SCAN_T 1024
#define SCAN_C 49   // ceil(50000/1024)
__global__ __launch_bounds__(SCAN_T) void k_scan(int n) {
    __shared__ int ss[SCAN_T];
    int t = threadIdx.x;
    int base = t * SCAN_C;
    int local = 0;
#pragma unroll
    for (int j = 0; j < SCAN_C; j++) {
        int idx = base + j;
        if (idx < n) local += g_deg[idx];
    }
    ss[t] = local;
    __syncthreads();
    for (int off = 1; off < SCAN_T; off <<= 1) {
        int v = (t >= off) ? ss[t - off] : 0;
        __syncthreads();
        ss[t] += v;
        __syncthreads();
    }
    int run = ss[t] - local;   // exclusive prefix
#pragma unroll
    for (int j = 0; j < SCAN_C; j++) {
        int idx = base + j;
        if (idx < n) {
            g_rowptr[idx] = run;
            g_cursor[idx] = run;
            run += g_deg[idx];
        }
    }
    if (t == SCAN_T - 1) g_rowptr[n] = ss[SCAN_T - 1];
}

// ---------------- hybrid: GEMM1 (tf32, fused logits, fp16 out) + CSR scatter ----
// blocks [0, nG1): gemm tiles; blocks [nG1, ...): scatter chunks (independent work).
__global__ __launch_bounds__(256) void k_g1s(const float* __restrict__ x,
                                             const float* __restrict__ W1,
                                             const float* __restrict__ a_src,
                                             const float* __restrict__ a_dst,
                                             const int* __restrict__ ei,
                                             int E, int ET, int n, int nG1) {
    __shared__ unsigned As[128][36];
    __shared__ unsigned Bt[128][36];
    if (blockIdx.x >= nG1) {
        int i = (blockIdx.x - nG1) * 256 + threadIdx.x;
        if (i < ET) {
            int src, dst;
            if (i < E) { src = ei[i]; dst = ei[E + i]; }
            else       { src = dst = i - E; }
            int pos = atomicAdd(&g_cursor[dst], 1);
            g_csrsrc[pos] = src;
        }
        return;
    }
    int tid  = threadIdx.x;
    int lane = tid & 31;
    int wid  = tid >> 5;
    int wm   = wid & 3;
    int wn   = wid >> 2;
    int rowBase = blockIdx.x * 128;

    float acc[2][8][4];
#pragma unroll
    for (int mi = 0; mi < 2; mi++)
#pragma unroll
        for (int ni = 0; ni < 8; ni++)
#pragma unroll
            for (int j = 0; j < 4; j++) acc[mi][ni][j] = 0.f;

    for (int k0 = 0; k0 < INDIM; k0 += 32) {
#pragma unroll
        for (int t = 0; t < 4; t++) {
            int f = tid + t * 256;
            int r = f >> 3, c4 = f & 7;
            int gr = rowBase + r;
            float4 v = (gr < n) ? ((const float4*)x)[gr * (INDIM/4) + (k0 >> 2) + c4]
                                : make_float4(0.f, 0.f, 0.f, 0.f);
            uint4 u = make_uint4(f2tf(v.x), f2tf(v.y), f2tf(v.z), f2tf(v.w));
            *(uint4*)&As[r][c4 * 4] = u;
        }
#pragma unroll
        for (int t = 0; t < 16; t++) {
            int e = tid + t * 256;
            int k = e >> 7, nn = e & 127;
            Bt[nn][k] = f2tf(W1[(k0 + k) * D1 + nn]);
        }
        __syncthreads();
#pragma unroll
        for (int k8 = 0; k8 < 4; k8++) {
            int kb = k8 * 8;
            unsigned a[2][4], b[8][2];
#pragma unroll
            for (int mi = 0; mi < 2; mi++) {
                int r = wm * 32 + mi * 16 + (lane >> 2);
                a[mi][0] = As[r][kb + (lane & 3)];
                a[mi][1] = As[r + 8][kb + (lane & 3)];
                a[mi][2] = As[r][kb + (lane & 3) + 4];
                a[mi][3] = As[r + 8][kb + (lane & 3) + 4];
            }
#pragma unroll
            for (int ni = 0; ni < 8; ni++) {
                int c = wn * 64 + ni * 8 + (lane >> 2);
                b[ni][0] = Bt[c][kb + (lane & 3)];
                b[ni][1] = Bt[c][kb + (lane & 3) + 4];
            }
#pragma unroll
            for (int mi = 0; mi < 2; mi++)
#pragma unroll
                for (int ni = 0; ni < 8; ni++)
                    mma_tf32(acc[mi][ni], a[mi], b[ni]);
        }
        __syncthreads();
    }
    // epilogue: fp16 store + fused attention-logit dots
    float aS[8][2], aD[8][2];
#pragma unroll
    for (int ni = 0; ni < 8; ni++) {
        int c = wn * 64 + ni * 8 + 2 * (lane & 3);
        float2 v = *(const float2*)&a_src[c]; aS[ni][0] = v.x; aS[ni][1] = v.y;
        float2 w = *(const float2*)&a_dst[c]; aD[ni][0] = w.x; aD[ni][1] = w.y;
    }
#pragma unroll
    for (int mi = 0; mi < 2; mi++) {
        int r0 = rowBase + wm * 32 + mi * 16 + (lane >> 2);
        float sS[2][2] = {{0.f,0.f},{0.f,0.f}}, sD[2][2] = {{0.f,0.f},{0.f,0.f}};
#pragma unroll
        for (int ni = 0; ni < 8; ni++) {
            int c = wn * 64 + ni * 8 + 2 * (lane & 3);
            if (r0 < n)
                *(__half2*)&g_h1h[r0 * D1 + c] = __floats2half2_rn(acc[mi][ni][0], acc[mi][ni][1]);
            if (r0 + 8 < n)
                *(__half2*)&g_h1h[(r0 + 8) * D1 + c] = __floats2half2_rn(acc[mi][ni][2], acc[mi][ni][3]);
            int hd = ni >> 2;
            sS[0][hd] += acc[mi][ni][0]*aS[ni][0] + acc[mi][ni][1]*aS[ni][1];
            sD[0][hd] += acc[mi][ni][0]*aD[ni][0] + acc[mi][ni][1]*aD[ni][1];
            sS[1][hd] += acc[mi][ni][2]*aS[ni][0] + acc[mi][ni][3]*aS[ni][1];
            sD[1][hd] += acc[mi][ni][2]*aD[ni][0] + acc[mi][ni][3]*aD[ni][1];
        }
#pragma unroll
        for (int rr = 0; rr < 2; rr++)
#pragma unroll
            for (int hd = 0; hd < 2; hd++) {
                float s = sS[rr][hd], d = sD[rr][hd];
                s += __shfl_xor_sync(0xffffffffu, s, 1);
                s += __shfl_xor_sync(0xffffffffu, s, 2);
                d += __shfl_xor_sync(0xffffffffu, d, 1);
                d += __shfl_xor_sync(0xffffffffu, d, 2);
                int r = r0 + rr * 8;
                if ((lane & 3) == 0 && r < n) {
                    g_als1[r * 4 + wn * 2 + hd] = s;
                    g_ald1[r * 4 + wn * 2 + hd] = d;
                }
            }
    }
}

// ---------------- layer-1 aggregation: warp per dst node, fp16 gather ----------------
__global__ __launch_bounds__(256) void k_agg1(int n) {
    int node = blockIdx.x * 8 + (threadIdx.x >> 5);
    if (node >= n) return;
    int l = threadIdx.x & 31;
    int beg = g_rowptr[node], end = g_rowptr[node + 1];
    float dv = pick4(*((const float4*)g_ald1 + node), l);
    const uint2* hb = (const uint2*)g_h1h;   // 8B per lane slot, 32 slots per row
    float ax = 0.f, ay = 0.f, az = 0.f, aw = 0.f, psum = 0.f;
    int e = beg;
    for (; e + 2 <= end; e += 2) {
        int s0 = __ldg(&g_csrsrc[e]);
        int s1 = __ldg(&g_csrsrc[e + 1]);
        float4 q0 = __ldg((const float4*)g_als1 + s0);
        float4 q1 = __ldg((const float4*)g_als1 + s1);
        uint2 u0 = __ldg(hb + s0 * 32 + l);
        uint2 u1 = __ldg(hb + s1 * 32 + l);
        float p0 = __expf(lrelu(pick4(q0, l) + dv));
        float p1 = __expf(lrelu(pick4(q1, l) + dv));
        float2 f0a = __half22float2(*(__half2*)&u0.x);
        float2 f0b = __half22float2(*(__half2*)&u0.y);
        float2 f1a = __half22float2(*(__half2*)&u1.x);
        float2 f1b = __half22float2(*(__half2*)&u1.y);
        ax += p0 * f0a.x + p1 * f1a.x;  ay += p0 * f0a.y + p1 * f1a.y;
        az += p0 * f0b.x + p1 * f1b.x;  aw += p0 * f0b.y + p1 * f1b.y;
        psum += p0 + p1;
    }
    if (e < end) {
        int s0 = __ldg(&g_csrsrc[e]);
        float4 q0 = __ldg((const float4*)g_als1 + s0);
        uint2 u0 = __ldg(hb + s0 * 32 + l);
        float p0 = __expf(lrelu(pick4(q0, l) + dv));
        float2 f0a = __half22float2(*(__half2*)&u0.x);
        float2 f0b = __half22float2(*(__half2*)&u0.y);
        ax += p0 * f0a.x;  ay += p0 * f0a.y;
        az += p0 * f0b.x;  aw += p0 * f0b.y;
        psum += p0;
    }
    float inv = __fdividef(1.f, psum);
    ((float4*)g_out1)[node * 32 + l] = make_float4(ax * inv, ay * inv, az * inv, aw * inv);
}

// ---------------- GEMM2 (tf32, fused elu-on-load + logits, fp16 out) ----------------
__global__ __launch_bounds__(256) void k_gemm2(const float* __restrict__ W2,
                                               const float* __restrict__ b1,
                                               const float* __restrict__ a_src,
                                               const float* __restrict__ a_dst, int n) {
    __shared__ unsigned As[128][36];
    __shared__ unsigned Bt[OUTC][132];
    int tid  = threadIdx.x;
    int lane = tid & 31;
    int wid  = tid >> 5;
    int rowBase = blockIdx.x * 128;

    for (int e = tid; e < D1 * OUTC; e += 256) {
        int k = e / OUTC, nn = e - k * OUTC;
        Bt[nn][k] = f2tf(W2[k * OUTC + nn]);
    }

    float acc[5][4];
#pragma unroll
    for (int ni = 0; ni < 5; ni++)
#pragma unroll
        for (int j = 0; j < 4; j++) acc[ni][j] = 0.f;

    for (int kt = 0; kt < 4; kt++) {
        __syncthreads();
#pragma unroll
        for (int t = 0; t < 4; t++) {
            int f = tid + t * 256;
            int r = f >> 3, c4 = f & 7;
            int gr = rowBase + r;
            float4 v = make_float4(0.f, 0.f, 0.f, 0.f);
            if (gr < n) {
                v = ((const float4*)g_out1)[gr * 32 + kt * 8 + c4];
                float4 b = ((const float4*)b1)[kt * 8 + c4];
                v.x += b.x;  v.y += b.y;  v.z += b.z;  v.w += b.w;
                v.x = v.x > 0.f ? v.x : expm1f(v.x);
                v.y = v.y > 0.f ? v.y : expm1f(v.y);
                v.z = v.z > 0.f ? v.z : expm1f(v.z);
                v.w = v.w > 0.f ? v.w : expm1f(v.w);
            }
            uint4 u = make_uint4(f2tf(v.x), f2tf(v.y), f2tf(v.z), f2tf(v.w));
            *(uint4*)&As[r][c4 * 4] = u;
        }
        __syncthreads();
#pragma unroll
        for (int k8 = 0; k8 < 4; k8++) {
            int kb = k8 * 8;
            unsigned a[4], b[5][2];
            int r = wid * 16 + (lane >> 2);
            a[0] = As[r][kb + (lane & 3)];
            a[1] = As[r + 8][kb + (lane & 3)];
            a[2] = As[r][kb + (lane & 3) + 4];
            a[3] = As[r + 8][kb + (lane & 3) + 4];
#pragma unroll
            for (int ni = 0; ni < 5; ni++) {
                int c = ni * 8 + (lane >> 2);
                b[ni][0] = Bt[c][kt * 32 + kb + (lane & 3)];
                b[ni][1] = Bt[c][kt * 32 + kb + (lane & 3) + 4];
            }
#pragma unroll
            for (int ni = 0; ni < 5; ni++)
                mma_tf32(acc[ni], a, b[ni]);
        }
    }
    // epilogue: fp16 store + fused logit dots
    int r0 = rowBase + wid * 16 + (lane >> 2);
    float aS[5][2], aD[5][2];
#pragma unroll
    for (int ni = 0; ni < 5; ni++) {
        int c = ni * 8 + 2 * (lane & 3);
        float2 v = *(const float2*)&a_src[c]; aS[ni][0] = v.x; aS[ni][1] = v.y;
        float2 w = *(const float2*)&a_dst[c]; aD[ni][0] = w.x; aD[ni][1] = w.y;
    }
    float sS[2] = {0.f, 0.f}, sD[2] = {0.f, 0.f};
#pragma unroll
    for (int ni = 0; ni < 5; ni++) {
        int c = ni * 8 + 2 * (lane & 3);
        if (r0 < n)
            *(__half2*)&g_h2h[r0 * OUTC + c] = __floats2half2_rn(acc[ni][0], acc[ni][1]);
        if (r0 + 8 < n)
            *(__half2*)&g_h2h[(r0 + 8) * OUTC + c] = __floats2half2_rn(acc[ni][2], acc[ni][3]);
        sS[0] += acc[ni][0]*aS[ni][0] + acc[ni][1]*aS[ni][1];
        sD[0] += acc[ni][0]*aD[ni][0] + acc[ni][1]*aD[ni][1];
        sS[1] += acc[ni][2]*aS[ni][0] + acc[ni][3]*aS[ni][1];
        sD[1] += acc[ni][2]*aD[ni][0] + acc[ni][3]*aD[ni][1];
    }
#pragma unroll
    for (int rr = 0; rr < 2; rr++) {
        float s = sS[rr], d = sD[rr];
        s += __shfl_xor_sync(0xffffffffu, s, 1);
        s += __shfl_xor_sync(0xffffffffu, s, 2);
        d += __shfl_xor_sync(0xffffffffu, d, 1);
        d += __shfl_xor_sync(0xffffffffu, d, 2);
        int r = r0 + rr * 8;
        if ((lane & 3) == 0 && r < n) { g_als2[r] = s; g_ald2[r] = d; }
    }
}

// ---------------- layer-2 aggregation + bias + log_softmax (warp per dst node) ---
__global__ __launch_bounds__(256) void k_agg2(float* __restrict__ out,
                                              const float* __restrict__ b2, int n) {
    int node = blockIdx.x * 8 + (threadIdx.x >> 5);
    if (node >= n) return;
    int l = threadIdx.x & 31;
    int beg = g_rowptr[node], end = g_rowptr[node + 1];
    float dv = g_ald2[node];
    float aa = 0.f, ab = 0.f, psum = 0.f;
    int e = beg;
    for (; e + 2 <= end; e += 2) {
        int s0 = __ldg(&g_csrsrc[e]);
        int s1 = __ldg(&g_csrsrc[e + 1]);
        float v0 = __ldg(&g_als2[s0]);
        float v1 = __ldg(&g_als2[s1]);
        float h0 = __half2float(__ldg(&g_h2h[s0 * OUTC + l]));
        float h1 = __half2float(__ldg(&g_h2h[s1 * OUTC + l]));
        float p0 = __expf(lrelu(v0 + dv));
        float p1 = __expf(lrelu(v1 + dv));
        aa += p0 * h0 + p1 * h1;
        if (l < 8) {
            float g0 = __half2float(__ldg(&g_h2h[s0 * OUTC + 32 + l]));
            float g1 = __half2float(__ldg(&g_h2h[s1 * OUTC + 32 + l]));
            ab += p0 * g0 + p1 * g1;
        }
        psum += p0 + p1;
    }
    if (e < end) {
        int s0 = __ldg(&g_csrsrc[e]);
        float v0 = __ldg(&g_als2[s0]);
        float p0 = __expf(lrelu(v0 + dv));
        aa += p0 * __half2float(__ldg(&g_h2h[s0 * OUTC + l]));
        if (l < 8) ab += p0 * __half2float(__ldg(&g_h2h[s0 * OUTC + 32 + l]));
        psum += p0;
    }
    float inv = __fdividef(1.f, psum);
    float a = aa * inv + b2[l];
    float b = (l < 8) ? ab * inv + b2[32 + l] : __int_as_float(0xff800000);
    float mx = fmaxf(a, b);
#pragma unroll
    for (int o = 16; o; o >>= 1) mx = fmaxf(mx, __shfl_xor_sync(0xffffffffu, mx, o));
    float se = __expf(a - mx) + ((l < 8) ? __expf(b - mx) : 0.f);
#pragma unroll
    for (int o = 16; o; o >>= 1) se += __shfl_xor_sync(0xffffffffu, se, o);
    float lse = logf(se);
    out[node * OUTC + l] = a - mx - lse;
    if (l < 8) out[node * OUTC + 32 + l] = b - mx - lse;
}

// ---------------- launch ----------------
static inline int cdiv(int a, int b) { return (a + b - 1) / b; }

extern "C" void kernel_launch(void* const* d_in, const int* in_sizes, int n_in,
                              void* d_out, int out_size) {
    const float* x      = (const float*)d_in[0];
    const int*   ei     = (const int*)  d_in[1];
    const float* W1     = (const float*)d_in[2];
    const float* a_src1 = (const float*)d_in[3];
    const float* a_dst1 = (const float*)d_in[4];
    const float* b1     = (const float*)d_in[5];
    const float* W2     = (const float*)d_in[6];
    const float* a_src2 = (const float*)d_in[7];
    const float* a_dst2 = (const float*)d_in[8];
    const float* b2     = (const float*)d_in[9];
    float* out = (float*)d_out;

    const int n  = NNODES;
    const int E  = in_sizes[1] / 2;
    const int ET = E + n;
    const int nG1 = cdiv(n, 128);

    k_deg_init <<<cdiv(n, 256), 256>>>(n);
    k_deg_count<<<cdiv(E, 256), 256>>>(ei, E);
    k_scan     <<<1, SCAN_T>>>(n);
    k_g1s      <<<nG1 + cdiv(ET, 256), 256>>>(x, W1, a_src1, a_dst1, ei, E, ET, n, nG1);
    k_agg1     <<<cdiv(n, 8), 256>>>(n);
    k_gemm2    <<<cdiv(n, 128), 256>>>(W2, b1, a_src2, a_dst2, n);
    k_agg2     <<<cdiv(n, 8), 256>>>(out, b2, n);
}

// round 6
// speedup vs baseline: 1.8388x; 1.1308x over previous
#include <cuda_runtime.h>
#include <cuda_fp16.h>

#define NNODES 50000
#define INDIM  256
#define HEADS1 4
#define D1     128      // HEADS1*CH1
#define OUTC   40
#define MAXE   800000
#define MAXET  (MAXE + NNODES)

// ---------------- scratch (static device globals; no allocation) ----------------
__device__ __half g_h1h [NNODES * D1];    // x @ W1, fp16 (gather payload)
__device__ float  g_out1[NNODES * D1];    // layer1 aggregated, normalized + bias + ELU
__device__ float  g_als1[NNODES * HEADS1];
__device__ float  g_ald1[NNODES * HEADS1];
__device__ __half g_h2h [NNODES * OUTC];  // layer2 pre-agg features, fp16
__device__ float  g_als2[NNODES];
__device__ float  g_ald2[NNODES];
__device__ float  g_W1t [D1 * INDIM];     // W1 transposed [n][k]
__device__ float  g_W2t [OUTC * D1];      // W2 transposed [n][k]
// CSR (dst-sorted), built once per launch, shared by both layers
__device__ int g_deg    [NNODES];
__device__ int g_rowptr [NNODES + 1];
__device__ int g_cursor [NNODES];
__device__ int g_csrsrc [MAXET];

// ---------------- helpers ----------------
__device__ __forceinline__ float lrelu(float x) { return x > 0.f ? x : 0.2f * x; }

__device__ __forceinline__ void mma_tf32(float c[4], const unsigned a[4], const unsigned b[2]) {
    asm volatile("mma.sync.aligned.m16n8k8.row.col.f32.tf32.tf32.f32 "
                 "{%0,%1,%2,%3}, {%4,%5,%6,%7}, {%8,%9}, {%0,%1,%2,%3};"
                 : "+f"(c[0]), "+f"(c[1]), "+f"(c[2]), "+f"(c[3])
                 : "r"(a[0]), "r"(a[1]), "r"(a[2]), "r"(a[3]), "r"(b[0]), "r"(b[1]));
}

__device__ __forceinline__ void cp16(void* smem, const void* gmem) {
    unsigned s = (unsigned)__cvta_generic_to_shared(smem);
    asm volatile("cp.async.cg.shared.global [%0], [%1], 16;" :: "r"(s), "l"(gmem));
}
__device__ __forceinline__ void cp16z(void* smem, const void* gmem, bool valid) {
    unsigned s = (unsigned)__cvta_generic_to_shared(smem);
    int sz = valid ? 16 : 0;
    asm volatile("cp.async.cg.shared.global [%0], [%1], 16, %2;" :: "r"(s), "l"(gmem), "r"(sz));
}
__device__ __forceinline__ void cpcommit() { asm volatile("cp.async.commit_group;"); }
template<int N> __device__ __forceinline__ void cpwait() {
    asm volatile("cp.async.wait_group %0;" :: "n"(N));
}

// pick head component (head = l>>3) from float4 of per-head logits
__device__ __forceinline__ float pick4(float4 q, int l) {
    float lo = (l & 8)  ? q.y : q.x;
    float hi = (l & 8)  ? q.w : q.z;
    return    (l & 16) ? hi : lo;
}

// ---------------- prep: transpose W1/W2, init deg=1 ----------------
__global__ __launch_bounds__(256) void k_prep(const float* __restrict__ W1,
                                              const float* __restrict__ W2, int n) {
    int i = blockIdx.x * blockDim.x + threadIdx.x;
    if (i < D1 * INDIM) {
        int nn = i & 127, k = i >> 7;
        g_W1t[nn * INDIM + k] = W1[k * D1 + nn];
    }
    int j = i - D1 * INDIM;
    if (j >= 0 && j < OUTC * D1) {
        int k = j / OUTC, nn = j - k * OUTC;
        g_W2t[nn * D1 + k] = W2[k * OUTC + nn];
    }
    int m = j - OUTC * D1;
    if (m >= 0 && m < n) g_deg[m] = 1;      // self-loop
}

__global__ __launch_bounds__(256) void k_count(const int* __restrict__ ei, int E) {
    int i = blockIdx.x * blockDim.x + threadIdx.x;
    if (i < E) atomicAdd(&g_deg[ei[E + i]], 1);
}

#define SCAN_T 1024
#define SCAN_C 49   // ceil(50000/1024)
__global__ __launch_bounds__(SCAN_T) void k_scan(int n) {
    __shared__ int ss[SCAN_T];
    int t = threadIdx.x;
    int base = t * SCAN_C;
    int local = 0;
#pragma unroll
    for (int j = 0; j < SCAN_C; j++) {
        int idx = base + j;
        if (idx < n) local += g_deg[idx];
    }
    ss[t] = local;
    __syncthreads();
    for (int off = 1; off < SCAN_T; off <<= 1) {
        int v = (t >= off) ? ss[t - off] : 0;
        __syncthreads();
        ss[t] += v;
        __syncthreads();
    }
    int run = ss[t] - local;   // exclusive prefix
#pragma unroll
    for (int j = 0; j < SCAN_C; j++) {
        int idx = base + j;
        if (idx < n) {
            g_rowptr[idx] = run;
            g_cursor[idx] = run;
            run += g_deg[idx];
        }
    }
    if (t == SCAN_T - 1) g_rowptr[n] = ss[SCAN_T - 1];
}

// ---------------- hybrid: GEMM1 (tf32, cp.async 2-stage, fused logits) + scatter ----
__global__ __launch_bounds__(256) void k_g1s(const float* __restrict__ x,
                                             const float* __restrict__ a_src,
                                             const float* __restrict__ a_dst,
                                             const int* __restrict__ ei,
                                             int E, int ET, int n, int nG1) {
    extern __shared__ unsigned sm[];     // A: 2*128*36, B: 2*128*36 (73728 B)
    if (blockIdx.x >= nG1) {
        int i = (blockIdx.x - nG1) * 256 + threadIdx.x;
        if (i < ET) {
            int src, dst;
            if (i < E) { src = ei[i]; dst = ei[E + i]; }
            else       { src = dst = i - E; }
            int pos = atomicAdd(&g_cursor[dst], 1);
            g_csrsrc[pos] = src;
        }
        return;
    }
    unsigned* Asm = sm;
    unsigned* Bsm = sm + 2 * 4608;
    int tid  = threadIdx.x;
    int lane = tid & 31;
    int wid  = tid >> 5;
    int wm   = wid & 3;
    int wn   = wid >> 2;
    int rowBase = blockIdx.x * 128;

    auto stage = [&](int s, int kt) {
        int k0 = kt * 32;
#pragma unroll
        for (int t = 0; t < 4; t++) {
            int f = tid + t * 256;
            int r = f >> 3, c4 = f & 7;
            int gr = rowBase + r;
            bool valid = (gr < n);
            const float* p = x + (size_t)(valid ? gr : 0) * INDIM + k0 + c4 * 4;
            cp16z(&Asm[s * 4608 + r * 36 + c4 * 4], p, valid);
        }
#pragma unroll
        for (int t = 0; t < 4; t++) {
            int f = tid + t * 256;
            int r = f >> 3, c4 = f & 7;
            cp16(&Bsm[s * 4608 + r * 36 + c4 * 4], g_W1t + r * INDIM + k0 + c4 * 4);
        }
    };

    float acc[2][8][4];
#pragma unroll
    for (int mi = 0; mi < 2; mi++)
#pragma unroll
        for (int ni = 0; ni < 8; ni++)
#pragma unroll
            for (int j = 0; j < 4; j++) acc[mi][ni][j] = 0.f;

    stage(0, 0); cpcommit();
    for (int kt = 0; kt < 8; kt++) {
        if (kt < 7) { stage((kt + 1) & 1, kt + 1); cpcommit(); cpwait<1>(); }
        else        cpwait<0>();
        __syncthreads();
        const unsigned* A = Asm + (kt & 1) * 4608;
        const unsigned* B = Bsm + (kt & 1) * 4608;
#pragma unroll
        for (int k8 = 0; k8 < 4; k8++) {
            int kb = k8 * 8 + (lane & 3);
            unsigned a[2][4], b[8][2];
#pragma unroll
            for (int mi = 0; mi < 2; mi++) {
                int r = wm * 32 + mi * 16 + (lane >> 2);
                a[mi][0] = A[r * 36 + kb];
                a[mi][1] = A[(r + 8) * 36 + kb];
                a[mi][2] = A[r * 36 + kb + 4];
                a[mi][3] = A[(r + 8) * 36 + kb + 4];
            }
#pragma unroll
            for (int ni = 0; ni < 8; ni++) {
                int c = wn * 64 + ni * 8 + (lane >> 2);
                b[ni][0] = B[c * 36 + kb];
                b[ni][1] = B[c * 36 + kb + 4];
            }
#pragma unroll
            for (int mi = 0; mi < 2; mi++)
#pragma unroll
                for (int ni = 0; ni < 8; ni++)
                    mma_tf32(acc[mi][ni], a[mi], b[ni]);
        }
        __syncthreads();
    }
    // epilogue: fp16 store + fused attention-logit dots
    float aS[8][2], aD[8][2];
#pragma unroll
    for (int ni = 0; ni < 8; ni++) {
        int c = wn * 64 + ni * 8 + 2 * (lane & 3);
        float2 v = *(const float2*)&a_src[c]; aS[ni][0] = v.x; aS[ni][1] = v.y;
        float2 w = *(const float2*)&a_dst[c]; aD[ni][0] = w.x; aD[ni][1] = w.y;
    }
#pragma unroll
    for (int mi = 0; mi < 2; mi++) {
        int r0 = rowBase + wm * 32 + mi * 16 + (lane >> 2);
        float sS[2][2] = {{0.f,0.f},{0.f,0.f}}, sD[2][2] = {{0.f,0.f},{0.f,0.f}};
#pragma unroll
        for (int ni = 0; ni < 8; ni++) {
            int c = wn * 64 + ni * 8 + 2 * (lane & 3);
            if (r0 < n)
                *(__half2*)&g_h1h[r0 * D1 + c] = __floats2half2_rn(acc[mi][ni][0], acc[mi][ni][1]);
            if (r0 + 8 < n)
                *(__half2*)&g_h1h[(r0 + 8) * D1 + c] = __floats2half2_rn(acc[mi][ni][2], acc[mi][ni][3]);
            int hd = ni >> 2;
            sS[0][hd] += acc[mi][ni][0]*aS[ni][0] + acc[mi][ni][1]*aS[ni][1];
            sD[0][hd] += acc[mi][ni][0]*aD[ni][0] + acc[mi][ni][1]*aD[ni][1];
            sS[1][hd] += acc[mi][ni][2]*aS[ni][0] + acc[mi][ni][3]*aS[ni][1];
            sD[1][hd] += acc[mi][ni][2]*aD[ni][0] + acc[mi][ni][3]*aD[ni][1];
        }
#pragma unroll
        for (int rr = 0; rr < 2; rr++)
#pragma unroll
            for (int hd = 0; hd < 2; hd++) {
                float s = sS[rr][hd], d = sD[rr][hd];
                s += __shfl_xor_sync(0xffffffffu, s, 1);
                s += __shfl_xor_sync(0xffffffffu, s, 2);
                d += __shfl_xor_sync(0xffffffffu, d, 1);
                d += __shfl_xor_sync(0xffffffffu, d, 2);
                int r = r0 + rr * 8;
                if ((lane & 3) == 0 && r < n) {
                    g_als1[r * 4 + wn * 2 + hd] = s;
                    g_ald1[r * 4 + wn * 2 + hd] = d;
                }
            }
    }
}

// ---------------- layer-1 aggregation: warp per dst node + fused bias/ELU ----------
__global__ __launch_bounds__(256) void k_agg1(const float* __restrict__ b1, int n) {
    int node = blockIdx.x * 8 + (threadIdx.x >> 5);
    if (node >= n) return;
    int l = threadIdx.x & 31;
    int beg = g_rowptr[node], end = g_rowptr[node + 1];
    float dv = pick4(*((const float4*)g_ald1 + node), l);
    const uint2* hb = (const uint2*)g_h1h;
    float ax = 0.f, ay = 0.f, az = 0.f, aw = 0.f, psum = 0.f;
    int e = beg;
    for (; e + 4 <= end; e += 4) {
        int s0 = __ldg(&g_csrsrc[e]);
        int s1 = __ldg(&g_csrsrc[e + 1]);
        int s2 = __ldg(&g_csrsrc[e + 2]);
        int s3 = __ldg(&g_csrsrc[e + 3]);
        float4 q0 = __ldg((const float4*)g_als1 + s0);
        float4 q1 = __ldg((const float4*)g_als1 + s1);
        float4 q2 = __ldg((const float4*)g_als1 + s2);
        float4 q3 = __ldg((const float4*)g_als1 + s3);
        uint2 u0 = __ldg(hb + s0 * 32 + l);
        uint2 u1 = __ldg(hb + s1 * 32 + l);
        uint2 u2 = __ldg(hb + s2 * 32 + l);
        uint2 u3 = __ldg(hb + s3 * 32 + l);
        float p0 = __expf(lrelu(pick4(q0, l) + dv));
        float p1 = __expf(lrelu(pick4(q1, l) + dv));
        float p2 = __expf(lrelu(pick4(q2, l) + dv));
        float p3 = __expf(lrelu(pick4(q3, l) + dv));
        float2 fa, fb;
        fa = __half22float2(*(__half2*)&u0.x); fb = __half22float2(*(__half2*)&u0.y);
        ax += p0*fa.x; ay += p0*fa.y; az += p0*fb.x; aw += p0*fb.y;
        fa = __half22float2(*(__half2*)&u1.x); fb = __half22float2(*(__half2*)&u1.y);
        ax += p1*fa.x; ay += p1*fa.y; az += p1*fb.x; aw += p1*fb.y;
        fa = __half22float2(*(__half2*)&u2.x); fb = __half22float2(*(__half2*)&u2.y);
        ax += p2*fa.x; ay += p2*fa.y; az += p2*fb.x; aw += p2*fb.y;
        fa = __half22float2(*(__half2*)&u3.x); fb = __half22float2(*(__half2*)&u3.y);
        ax += p3*fa.x; ay += p3*fa.y; az += p3*fb.x; aw += p3*fb.y;
        psum += p0 + p1 + p2 + p3;
    }
    for (; e < end; e++) {
        int s0 = __ldg(&g_csrsrc[e]);
        float4 q0 = __ldg((const float4*)g_als1 + s0);
        uint2 u0 = __ldg(hb + s0 * 32 + l);
        float p0 = __expf(lrelu(pick4(q0, l) + dv));
        float2 fa = __half22float2(*(__half2*)&u0.x);
        float2 fb = __half22float2(*(__half2*)&u0.y);
        ax += p0*fa.x; ay += p0*fa.y; az += p0*fb.x; aw += p0*fb.y;
        psum += p0;
    }
    float inv = __fdividef(1.f, psum);
    float4 b = ((const float4*)b1)[l];
    float4 v = make_float4(ax * inv + b.x, ay * inv + b.y, az * inv + b.z, aw * inv + b.w);
    v.x = v.x > 0.f ? v.x : expm1f(v.x);
    v.y = v.y > 0.f ? v.y : expm1f(v.y);
    v.z = v.z > 0.f ? v.z : expm1f(v.z);
    v.w = v.w > 0.f ? v.w : expm1f(v.w);
    ((float4*)g_out1)[node * 32 + l] = v;
}

// ---------------- GEMM2 (tf32, stage-all-once, fused logits, fp16 out) ------------
__global__ __launch_bounds__(256) void k_gemm2(const float* __restrict__ a_src,
                                               const float* __restrict__ a_dst, int n) {
    extern __shared__ unsigned sm2[];    // A: 128*132, B: 40*132  (88704 B)
    unsigned* Asm = sm2;
    unsigned* Bsm = sm2 + 128 * 132;
    int tid  = threadIdx.x;
    int lane = tid & 31;
    int wid  = tid >> 5;
    int rowBase = blockIdx.x * 128;

#pragma unroll
    for (int t = 0; t < 16; t++) {
        int f = tid + t * 256;
        int r = f >> 5, c4 = f & 31;
        int gr = rowBase + r;
        bool valid = (gr < n);
        const float* p = g_out1 + (size_t)(valid ? gr : 0) * D1 + c4 * 4;
        cp16z(&Asm[r * 132 + c4 * 4], p, valid);
    }
#pragma unroll
    for (int t = 0; t < 5; t++) {
        int f = tid + t * 256;
        int r = f >> 5, c4 = f & 31;
        cp16(&Bsm[r * 132 + c4 * 4], g_W2t + r * D1 + c4 * 4);
    }
    cpcommit(); cpwait<0>();
    __syncthreads();

    float acc[5][4];
#pragma unroll
    for (int ni = 0; ni < 5; ni++)
#pragma unroll
        for (int j = 0; j < 4; j++) acc[ni][j] = 0.f;

#pragma unroll
    for (int kk = 0; kk < 16; kk++) {
        int kb = kk * 8 + (lane & 3);
        unsigned a[4], b[5][2];
        int r = wid * 16 + (lane >> 2);
        a[0] = Asm[r * 132 + kb];
        a[1] = Asm[(r + 8) * 132 + kb];
        a[2] = Asm[r * 132 + kb + 4];
        a[3] = Asm[(r + 8) * 132 + kb + 4];
#pragma unroll
        for (int ni = 0; ni < 5; ni++) {
            int c = ni * 8 + (lane >> 2);
            b[ni][0] = Bsm[c * 132 + kb];
            b[ni][1] = Bsm[c * 132 + kb + 4];
        }
#pragma unroll
        for (int ni = 0; ni < 5; ni++)
            mma_tf32(acc[ni], a, b[ni]);
    }
    // epilogue: fp16 store + fused logit dots
    int r0 = rowBase + wid * 16 + (lane >> 2);
    float aS[5][2], aD[5][2];
#pragma unroll
    for (int ni = 0; ni < 5; ni++) {
        int c = ni * 8 + 2 * (lane & 3);
        float2 v = *(const float2*)&a_src[c]; aS[ni][0] = v.x; aS[ni][1] = v.y;
        float2 w = *(const float2*)&a_dst[c]; aD[ni][0] = w.x; aD[ni][1] = w.y;
    }
    float sS[2] = {0.f, 0.f}, sD[2] = {0.f, 0.f};
#pragma unroll
    for (int ni = 0; ni < 5; ni++) {
        int c = ni * 8 + 2 * (lane & 3);
        if (r0 < n)
            *(__half2*)&g_h2h[r0 * OUTC + c] = __floats2half2_rn(acc[ni][0], acc[ni][1]);
        if (r0 + 8 < n)
            *(__half2*)&g_h2h[(r0 + 8) * OUTC + c] = __floats2half2_rn(acc[ni][2], acc[ni][3]);
        sS[0] += acc[ni][0]*aS[ni][0] + acc[ni][1]*aS[ni][1];
        sD[0] += acc[ni][0]*aD[ni][0] + acc[ni][1]*aD[ni][1];
        sS[1] += acc[ni][2]*aS[ni][0] + acc[ni][3]*aS[ni][1];
        sD[1] += acc[ni][2]*aD[ni][0] + acc[ni][3]*aD[ni][1];
    }
#pragma unroll
    for (int rr = 0; rr < 2; rr++) {
        float s = sS[rr], d = sD[rr];
        s += __shfl_xor_sync(0xffffffffu, s, 1);
        s += __shfl_xor_sync(0xffffffffu, s, 2);
        d += __shfl_xor_sync(0xffffffffu, d, 1);
        d += __shfl_xor_sync(0xffffffffu, d, 2);
        int r = r0 + rr * 8;
        if ((lane & 3) == 0 && r < n) { g_als2[r] = s; g_ald2[r] = d; }
    }
}

// ---------------- layer-2 aggregation + bias + log_softmax (warp per dst node) ---
__global__ __launch_bounds__(256) void k_agg2(float* __restrict__ out,
                                              const float* __restrict__ b2, int n) {
    int node = blockIdx.x * 8 + (threadIdx.x >> 5);
    if (node >= n) return;
    int l = threadIdx.x & 31;
    int beg = g_rowptr[node], end = g_rowptr[node + 1];
    float dv = g_ald2[node];
    float aa = 0.f, ab = 0.f, psum = 0.f;
    int e = beg;
    for (; e + 2 <= end; e += 2) {
        int s0 = __ldg(&g_csrsrc[e]);
        int s1 = __ldg(&g_csrsrc[e + 1]);
        float v0 = __ldg(&g_als2[s0]);
        float v1 = __ldg(&g_als2[s1]);
        float h0 = __half2float(__ldg(&g_h2h[s0 * OUTC + l]));
        float h1 = __half2float(__ldg(&g_h2h[s1 * OUTC + l]));
        float p0 = __expf(lrelu(v0 + dv));
        float p1 = __expf(lrelu(v1 + dv));
        aa += p0 * h0 + p1 * h1;
        if (l < 8) {
            float g0 = __half2float(__ldg(&g_h2h[s0 * OUTC + 32 + l]));
            float g1 = __half2float(__ldg(&g_h2h[s1 * OUTC + 32 + l]));
            ab += p0 * g0 + p1 * g1;
        }
        psum += p0 + p1;
    }
    if (e < end) {
        int s0 = __ldg(&g_csrsrc[e]);
        float v0 = __ldg(&g_als2[s0]);
        float p0 = __expf(lrelu(v0 + dv));
        aa += p0 * __half2float(__ldg(&g_h2h[s0 * OUTC + l]));
        if (l < 8) ab += p0 * __half2float(__ldg(&g_h2h[s0 * OUTC + 32 + l]));
        psum += p0;
    }
    float inv = __fdividef(1.f, psum);
    float a = aa * inv + b2[l];
    float b = (l < 8) ? ab * inv + b2[32 + l] : __int_as_float(0xff800000);
    float mx = fmaxf(a, b);
#pragma unroll
    for (int o = 16; o; o >>= 1) mx = fmaxf(mx, __shfl_xor_sync(0xffffffffu, mx, o));
    float se = __expf(a - mx) + ((l < 8) ? __expf(b - mx) : 0.f);
#pragma unroll
    for (int o = 16; o; o >>= 1) se += __shfl_xor_sync(0xffffffffu, se, o);
    float lse = logf(se);
    out[node * OUTC + l] = a - mx - lse;
    if (l < 8) out[node * OUTC + 32 + l] = b - mx - lse;
}

// ---------------- launch ----------------
static inline int cdiv(int a, int b) { return (a + b - 1) / b; }

extern "C" void kernel_launch(void* const* d_in, const int* in_sizes, int n_in,
                              void* d_out, int out_size) {
    const float* x      = (const float*)d_in[0];
    const int*   ei     = (const int*)  d_in[1];
    const float* W1     = (const float*)d_in[2];
    const float* a_src1 = (const float*)d_in[3];
    const float* a_dst1 = (const float*)d_in[4];
    const float* b1     = (const float*)d_in[5];
    const float* W2     = (const float*)d_in[6];
    const float* a_src2 = (const float*)d_in[7];
    const float* a_dst2 = (const float*)d_in[8];
    const float* b2     = (const float*)d_in[9];
    float* out = (float*)d_out;

    const int n  = NNODES;
    const int E  = in_sizes[1] / 2;
    const int ET = E + n;
    const int nG1 = cdiv(n, 128);
    const int SM1 = 2 * 4608 * 2 * 4;            // 73728 B
    const int SM2 = (128 * 132 + 40 * 132) * 4;  // 88704 B

    cudaFuncSetAttribute(k_g1s,   cudaFuncAttributeMaxDynamicSharedMemorySize, SM1);
    cudaFuncSetAttribute(k_gemm2, cudaFuncAttributeMaxDynamicSharedMemorySize, SM2);

    const int prepW = D1 * INDIM + OUTC * D1 + n;
    k_prep <<<cdiv(prepW, 256), 256>>>(W1, W2, n);
    k_count<<<cdiv(E, 256), 256>>>(ei, E);
    k_scan <<<1, SCAN_T>>>(n);
    k_g1s  <<<nG1 + cdiv(ET, 256), 256, SM1>>>(x, a_src1, a_dst1, ei, E, ET, n, nG1);
    k_agg1 <<<cdiv(n, 8), 256>>>(b1, n);
    k_gemm2<<<cdiv(n, 128), 256, SM2>>>(a_src2, a_dst2, n);
    k_agg2 <<<cdiv(n, 8), 256>>>(out, b2, n);
}

// round 7
// speedup vs baseline: 2.6287x; 1.4296x over previous
#include <cuda_runtime.h>
#include <cuda_fp16.h>

#define NNODES 50000
#define INDIM  256
#define D1     128
#define OUTC   40
#define MAXE   800000
#define MAXET  (MAXE + NNODES)
#define NBLK   196          // cdiv(NNODES,256)

// ---------------- scratch ----------------
__device__ __half g_W1h [D1 * INDIM];     // W1^T fp16 [n][k]
__device__ __half g_W2h [OUTC * D1];      // W2^T fp16 [n][k]
__device__ __half g_h1h [NNODES * D1];    // x@W1 fp16 (gather payload)
__device__ __half g_out1h[NNODES * D1];   // elu(agg1+b1) fp16 (gemm2 input)
__device__ __half g_h2h [NNODES * OUTC];
__device__ float  g_als1[NNODES * 4];
__device__ float  g_ald1[NNODES * 4];
__device__ float  g_als2[NNODES];
__device__ float  g_ald2[NNODES];
__device__ int g_deg   [NNODES];
__device__ int g_epos  [MAXE];
__device__ int g_rowptr[NNODES + 1];
__device__ int g_bsum  [256];
__device__ int g_boff  [256];
__device__ int g_csrsrc[MAXET];

// ---------------- helpers ----------------
__device__ __forceinline__ float lrelu(float x) { return x > 0.f ? x : 0.2f * x; }

__device__ __forceinline__ void mma_f16(float c[4], const unsigned a[4], const unsigned b[2]) {
    asm volatile("mma.sync.aligned.m16n8k16.row.col.f32.f16.f16.f32 "
                 "{%0,%1,%2,%3}, {%4,%5,%6,%7}, {%8,%9}, {%0,%1,%2,%3};"
                 : "+f"(c[0]), "+f"(c[1]), "+f"(c[2]), "+f"(c[3])
                 : "r"(a[0]), "r"(a[1]), "r"(a[2]), "r"(a[3]), "r"(b[0]), "r"(b[1]));
}

__device__ __forceinline__ void cp16(void* smem, const void* gmem) {
    unsigned s = (unsigned)__cvta_generic_to_shared(smem);
    asm volatile("cp.async.cg.shared.global [%0], [%1], 16;" :: "r"(s), "l"(gmem));
}
__device__ __forceinline__ void cpcommit() { asm volatile("cp.async.commit_group;"); }
template<int N> __device__ __forceinline__ void cpwait() {
    asm volatile("cp.async.wait_group %0;" :: "n"(N));
}

__device__ __forceinline__ float pick4(float4 q, int l) {
    float lo = (l & 8)  ? q.y : q.x;
    float hi = (l & 8)  ? q.w : q.z;
    return    (l & 16) ? hi : lo;
}

// ---------------- prep: W transposes (fp16) + deg=0 ----------------
__global__ __launch_bounds__(256) void k_prep(const float* __restrict__ W1,
                                              const float* __restrict__ W2, int n) {
    int i = blockIdx.x * blockDim.x + threadIdx.x;
    if (i < D1 * INDIM) {
        int nn = i & 127, k = i >> 7;
        g_W1h[nn * INDIM + k] = __float2half(W1[k * D1 + nn]);
    }
    int j = i - D1 * INDIM;
    if (j >= 0 && j < OUTC * D1) {
        int k = j / OUTC, nn = j - k * OUTC;
        g_W2h[nn * D1 + k] = __float2half(W2[k * OUTC + nn]);
    }
    int m = j - OUTC * D1;
    if (m >= 0 && m < n) g_deg[m] = 0;
}

// ---------------- count: per-edge rank via atomic return ----------------
__global__ __launch_bounds__(256) void k_count(const int* __restrict__ ei, int E) {
    int i = blockIdx.x * blockDim.x + threadIdx.x;
    if (i < E) g_epos[i] = atomicAdd(&g_deg[ei[E + i]], 1);
}

// ---------------- multi-block scan (rowptr over deg+1) ----------------
__global__ __launch_bounds__(256) void k_scanA(int n) {
    __shared__ int ss[256];
    int i = blockIdx.x * 256 + threadIdx.x;
    int v = (i < n) ? g_deg[i] + 1 : 0;
    ss[threadIdx.x] = v;
    __syncthreads();
    for (int off = 128; off; off >>= 1) {
        if (threadIdx.x < off) ss[threadIdx.x] += ss[threadIdx.x + off];
        __syncthreads();
    }
    if (threadIdx.x == 0) g_bsum[blockIdx.x] = ss[0];
}
__global__ __launch_bounds__(256) void k_scanB(int nblk, int n) {
    __shared__ int ss[256];
    int t = threadIdx.x;
    int v = (t < nblk) ? g_bsum[t] : 0;
    ss[t] = v;
    __syncthreads();
    for (int off = 1; off < 256; off <<= 1) {
        int u = (t >= off) ? ss[t - off] : 0;
        __syncthreads();
        ss[t] += u;
        __syncthreads();
    }
    if (t < nblk) g_boff[t] = ss[t] - v;
    if (t == 255) g_rowptr[n] = ss[255];
}
__global__ __launch_bounds__(256) void k_scanC(int n) {
    __shared__ int ss[256];
    int t = threadIdx.x;
    int i = blockIdx.x * 256 + t;
    int v = (i < n) ? g_deg[i] + 1 : 0;
    ss[t] = v;
    __syncthreads();
    for (int off = 1; off < 256; off <<= 1) {
        int u = (t >= off) ? ss[t - off] : 0;
        __syncthreads();
        ss[t] += u;
        __syncthreads();
    }
    if (i < n) {
        int rp = g_boff[blockIdx.x] + ss[t] - v;
        g_rowptr[i] = rp;
        g_csrsrc[rp] = i;        // self-loop at segment head
    }
}

// ---------------- hybrid: GEMM1 (fp16 mma, pipelined) + atomic-free scatter ------
__global__ __launch_bounds__(256) void k_g1s(const float* __restrict__ x,
                                             const float* __restrict__ a_src,
                                             const float* __restrict__ a_dst,
                                             const int* __restrict__ ei,
                                             int E, int n, int nG1, int nS) {
    __shared__ __half As[2][128 * 40];
    __shared__ __half Bs[2][128 * 40];
    int tid  = threadIdx.x;
    if (blockIdx.x >= nG1) {
        int stride = nS * 256;
        for (int i = (blockIdx.x - nG1) * 256 + tid; i < E; i += stride) {
            int src = __ldg(&ei[i]);
            int dst = __ldg(&ei[E + i]);
            int pos = __ldg(&g_epos[i]);
            g_csrsrc[g_rowptr[dst] + 1 + pos] = src;
        }
        return;
    }
    int lane = tid & 31;
    int wid  = tid >> 5;
    int wm   = wid & 3;
    int wn   = wid >> 2;
    int rowBase = blockIdx.x * 128;
    int gtg  = lane >> 2;       // group
    int tig  = lane & 3;

    float acc[2][8][4];
#pragma unroll
    for (int mi = 0; mi < 2; mi++)
#pragma unroll
        for (int ni = 0; ni < 8; ni++)
#pragma unroll
            for (int j = 0; j < 4; j++) acc[mi][ni][j] = 0.f;

    float4 ar[4];
    auto stageB = [&](int buf, int kt) {
#pragma unroll
        for (int t2 = 0; t2 < 2; t2++) {
            int f = tid + t2 * 256;
            int nn = f >> 2, c = f & 3;
            cp16(&Bs[buf][nn * 40 + c * 8], g_W1h + nn * INDIM + kt * 32 + c * 8);
        }
    };
    auto ldgA = [&](int kt) {
#pragma unroll
        for (int t2 = 0; t2 < 4; t2++) {
            int f = tid + t2 * 256;
            int r = f >> 3, c4 = f & 7;
            int gr = rowBase + r;
            ar[t2] = __ldg((const float4*)(x + (size_t)(gr < n ? gr : 0) * INDIM) + kt * 8 + c4);
        }
    };
    auto stsA = [&](int buf) {
#pragma unroll
        for (int t2 = 0; t2 < 4; t2++) {
            int f = tid + t2 * 256;
            int r = f >> 3, c4 = f & 7;
            __half2 h0 = __floats2half2_rn(ar[t2].x, ar[t2].y);
            __half2 h1 = __floats2half2_rn(ar[t2].z, ar[t2].w);
            uint2 u;
            u.x = *(unsigned*)&h0; u.y = *(unsigned*)&h1;
            *(uint2*)&As[buf][r * 40 + c4 * 4] = u;
        }
    };
    auto compute = [&](int buf) {
#pragma unroll
        for (int kk = 0; kk < 2; kk++) {
            int kb = kk * 16 + 2 * tig;
            unsigned a[2][4], b[8][2];
#pragma unroll
            for (int mi = 0; mi < 2; mi++) {
                int r = wm * 32 + mi * 16 + gtg;
                a[mi][0] = *(unsigned*)&As[buf][r * 40 + kb];
                a[mi][1] = *(unsigned*)&As[buf][(r + 8) * 40 + kb];
                a[mi][2] = *(unsigned*)&As[buf][r * 40 + kb + 8];
                a[mi][3] = *(unsigned*)&As[buf][(r + 8) * 40 + kb + 8];
            }
#pragma unroll
            for (int ni = 0; ni < 8; ni++) {
                int c = wn * 64 + ni * 8 + gtg;
                b[ni][0] = *(unsigned*)&Bs[buf][c * 40 + kb];
                b[ni][1] = *(unsigned*)&Bs[buf][c * 40 + kb + 8];
            }
#pragma unroll
            for (int mi = 0; mi < 2; mi++)
#pragma unroll
                for (int ni = 0; ni < 8; ni++)
                    mma_f16(acc[mi][ni], a[mi], b[ni]);
        }
    };

    stageB(0, 0); cpcommit();
    ldgA(0); stsA(0);
    stageB(1, 1); cpcommit();
    ldgA(1);
    cpwait<1>();
    __syncthreads();
#pragma unroll
    for (int kt = 0; kt < 8; kt++) {
        if (kt >= 1 && kt < 7) { stageB((kt + 1) & 1, kt + 1); cpcommit(); }
        compute(kt & 1);
        if (kt < 7) {
            stsA((kt + 1) & 1);
            if (kt < 6) ldgA(kt + 2);
            cpwait<0>();
            __syncthreads();
        }
    }
    // epilogue: fp16 store + fused attention-logit dots
    float aS[8][2], aD[8][2];
#pragma unroll
    for (int ni = 0; ni < 8; ni++) {
        int c = wn * 64 + ni * 8 + 2 * tig;
        float2 v = *(const float2*)&a_src[c]; aS[ni][0] = v.x; aS[ni][1] = v.y;
        float2 w = *(const float2*)&a_dst[c]; aD[ni][0] = w.x; aD[ni][1] = w.y;
    }
#pragma unroll
    for (int mi = 0; mi < 2; mi++) {
        int r0 = rowBase + wm * 32 + mi * 16 + gtg;
        float sS[2][2] = {{0.f,0.f},{0.f,0.f}}, sD[2][2] = {{0.f,0.f},{0.f,0.f}};
#pragma unroll
        for (int ni = 0; ni < 8; ni++) {
            int c = wn * 64 + ni * 8 + 2 * tig;
            if (r0 < n)
                *(__half2*)&g_h1h[r0 * D1 + c] = __floats2half2_rn(acc[mi][ni][0], acc[mi][ni][1]);
            if (r0 + 8 < n)
                *(__half2*)&g_h1h[(r0 + 8) * D1 + c] = __floats2half2_rn(acc[mi][ni][2], acc[mi][ni][3]);
            int hd = ni >> 2;
            sS[0][hd] += acc[mi][ni][0]*aS[ni][0] + acc[mi][ni][1]*aS[ni][1];
            sD[0][hd] += acc[mi][ni][0]*aD[ni][0] + acc[mi][ni][1]*aD[ni][1];
            sS[1][hd] += acc[mi][ni][2]*aS[ni][0] + acc[mi][ni][3]*aS[ni][1];
            sD[1][hd] += acc[mi][ni][2]*aD[ni][0] + acc[mi][ni][3]*aD[ni][1];
        }
#pragma unroll
        for (int rr = 0; rr < 2; rr++)
#pragma unroll
            for (int hd = 0; hd < 2; hd++) {
                float s = sS[rr][hd], d = sD[rr][hd];
                s += __shfl_xor_sync(0xffffffffu, s, 1);
                s += __shfl_xor_sync(0xffffffffu, s, 2);
                d += __shfl_xor_sync(0xffffffffu, d, 1);
                d += __shfl_xor_sync(0xffffffffu, d, 2);
                int r = r0 + rr * 8;
                if (tig == 0 && r < n) {
                    g_als1[r * 4 + wn * 2 + hd] = s;
                    g_ald1[r * 4 + wn * 2 + hd] = d;
                }
            }
    }
}

// ---------------- layer-1 aggregation (warp/node) + bias + ELU, fp16 out --------
__global__ __launch_bounds__(256) void k_agg1(const float* __restrict__ b1, int n) {
    int node = blockIdx.x * 8 + (threadIdx.x >> 5);
    if (node >= n) return;
    int l = threadIdx.x & 31;
    int beg = g_rowptr[node], end = g_rowptr[node + 1];
    float dv = pick4(*((const float4*)g_ald1 + node), l);
    const uint2* hb = (const uint2*)g_h1h;
    float ax = 0.f, ay = 0.f, az = 0.f, aw = 0.f, psum = 0.f;
    int e = beg;
    for (; e + 4 <= end; e += 4) {
        int s0 = __ldg(&g_csrsrc[e]);
        int s1 = __ldg(&g_csrsrc[e + 1]);
        int s2 = __ldg(&g_csrsrc[e + 2]);
        int s3 = __ldg(&g_csrsrc[e + 3]);
        float4 q0 = __ldg((const float4*)g_als1 + s0);
        float4 q1 = __ldg((const float4*)g_als1 + s1);
        float4 q2 = __ldg((const float4*)g_als1 + s2);
        float4 q3 = __ldg((const float4*)g_als1 + s3);
        uint2 u0 = __ldg(hb + s0 * 32 + l);
        uint2 u1 = __ldg(hb + s1 * 32 + l);
        uint2 u2 = __ldg(hb + s2 * 32 + l);
        uint2 u3 = __ldg(hb + s3 * 32 + l);
        float p0 = __expf(lrelu(pick4(q0, l) + dv));
        float p1 = __expf(lrelu(pick4(q1, l) + dv));
        float p2 = __expf(lrelu(pick4(q2, l) + dv));
        float p3 = __expf(lrelu(pick4(q3, l) + dv));
        float2 fa, fb;
        fa = __half22float2(*(__half2*)&u0.x); fb = __half22float2(*(__half2*)&u0.y);
        ax += p0*fa.x; ay += p0*fa.y; az += p0*fb.x; aw += p0*fb.y;
        fa = __half22float2(*(__half2*)&u1.x); fb = __half22float2(*(__half2*)&u1.y);
        ax += p1*fa.x; ay += p1*fa.y; az += p1*fb.x; aw += p1*fb.y;
        fa = __half22float2(*(__half2*)&u2.x); fb = __half22float2(*(__half2*)&u2.y);
        ax += p2*fa.x; ay += p2*fa.y; az += p2*fb.x; aw += p2*fb.y;
        fa = __half22float2(*(__half2*)&u3.x); fb = __half22float2(*(__half2*)&u3.y);
        ax += p3*fa.x; ay += p3*fa.y; az += p3*fb.x; aw += p3*fb.y;
        psum += p0 + p1 + p2 + p3;
    }
    for (; e < end; e++) {
        int s0 = __ldg(&g_csrsrc[e]);
        float4 q0 = __ldg((const float4*)g_als1 + s0);
        uint2 u0 = __ldg(hb + s0 * 32 + l);
        float p0 = __expf(lrelu(pick4(q0, l) + dv));
        float2 fa = __half22float2(*(__half2*)&u0.x);
        float2 fb = __half22float2(*(__half2*)&u0.y);
        ax += p0*fa.x; ay += p0*fa.y; az += p0*fb.x; aw += p0*fb.y;
        psum += p0;
    }
    float inv = __fdividef(1.f, psum);
    float4 b = ((const float4*)b1)[l];
    float4 v = make_float4(ax * inv + b.x, ay * inv + b.y, az * inv + b.z, aw * inv + b.w);
    v.x = v.x > 0.f ? v.x : expm1f(v.x);
    v.y = v.y > 0.f ? v.y : expm1f(v.y);
    v.z = v.z > 0.f ? v.z : expm1f(v.z);
    v.w = v.w > 0.f ? v.w : expm1f(v.w);
    __half2 h0 = __floats2half2_rn(v.x, v.y);
    __half2 h1 = __floats2half2_rn(v.z, v.w);
    uint2 u;
    u.x = *(unsigned*)&h0; u.y = *(unsigned*)&h1;
    *(uint2*)&g_out1h[node * D1 + l * 4] = u;
}

// ---------------- GEMM2 (fp16 mma, stage-all-once, fused logits) -----------------
__global__ __launch_bounds__(256) void k_gemm2(const float* __restrict__ a_src,
                                               const float* __restrict__ a_dst, int n) {
    __shared__ __half As2[128 * 136];
    __shared__ __half Bs2[OUTC * 136];
    int tid  = threadIdx.x;
    int lane = tid & 31;
    int wid  = tid >> 5;
    int gtg  = lane >> 2;
    int tig  = lane & 3;
    int rowBase = blockIdx.x * 128;

#pragma unroll
    for (int t2 = 0; t2 < 8; t2++) {
        int f = tid + t2 * 256;
        int r = f >> 4, c = f & 15;
        int gr = rowBase + r;
        cp16(&As2[r * 136 + c * 8], g_out1h + (size_t)(gr < n ? gr : 0) * D1 + c * 8);
    }
    for (int f = tid; f < OUTC * 16; f += 256) {
        int r = f >> 4, c = f & 15;
        cp16(&Bs2[r * 136 + c * 8], g_W2h + r * D1 + c * 8);
    }
    cpcommit(); cpwait<0>();
    __syncthreads();

    float acc[5][4];
#pragma unroll
    for (int ni = 0; ni < 5; ni++)
#pragma unroll
        for (int j = 0; j < 4; j++) acc[ni][j] = 0.f;

#pragma unroll
    for (int kk = 0; kk < 8; kk++) {
        int kb = kk * 16 + 2 * tig;
        unsigned a[4], b[5][2];
        int r = wid * 16 + gtg;
        a[0] = *(unsigned*)&As2[r * 136 + kb];
        a[1] = *(unsigned*)&As2[(r + 8) * 136 + kb];
        a[2] = *(unsigned*)&As2[r * 136 + kb + 8];
        a[3] = *(unsigned*)&As2[(r + 8) * 136 + kb + 8];
#pragma unroll
        for (int ni = 0; ni < 5; ni++) {
            int c = ni * 8 + gtg;
            b[ni][0] = *(unsigned*)&Bs2[c * 136 + kb];
            b[ni][1] = *(unsigned*)&Bs2[c * 136 + kb + 8];
        }
#pragma unroll
        for (int ni = 0; ni < 5; ni++)
            mma_f16(acc[ni], a, b[ni]);
    }
    int r0 = rowBase + wid * 16 + gtg;
    float aS[5][2], aD[5][2];
#pragma unroll
    for (int ni = 0; ni < 5; ni++) {
        int c = ni * 8 + 2 * tig;
        float2 v = *(const float2*)&a_src[c]; aS[ni][0] = v.x; aS[ni][1] = v.y;
        float2 w = *(const float2*)&a_dst[c]; aD[ni][0] = w.x; aD[ni][1] = w.y;
    }
    float sS[2] = {0.f, 0.f}, sD[2] = {0.f, 0.f};
#pragma unroll
    for (int ni = 0; ni < 5; ni++) {
        int c = ni * 8 + 2 * tig;
        if (r0 < n)
            *(__half2*)&g_h2h[r0 * OUTC + c] = __floats2half2_rn(acc[ni][0], acc[ni][1]);
        if (r0 + 8 < n)
            *(__half2*)&g_h2h[(r0 + 8) * OUTC + c] = __floats2half2_rn(acc[ni][2], acc[ni][3]);
        sS[0] += acc[ni][0]*aS[ni][0] + acc[ni][1]*aS[ni][1];
        sD[0] += acc[ni][0]*aD[ni][0] + acc[ni][1]*aD[ni][1];
        sS[1] += acc[ni][2]*aS[ni][0] + acc[ni][3]*aS[ni][1];
        sD[1] += acc[ni][2]*aD[ni][0] + acc[ni][3]*aD[ni][1];
    }
#pragma unroll
    for (int rr = 0; rr < 2; rr++) {
        float s = sS[rr], d = sD[rr];
        s += __shfl_xor_sync(0xffffffffu, s, 1);
        s += __shfl_xor_sync(0xffffffffu, s, 2);
        d += __shfl_xor_sync(0xffffffffu, d, 1);
        d += __shfl_xor_sync(0xffffffffu, d, 2);
        int r = r0 + rr * 8;
        if (tig == 0 && r < n) { g_als2[r] = s; g_ald2[r] = d; }
    }
}

// ---------------- layer-2 aggregation + bias + log_softmax (warp/node) ----------
// lane l<20 owns channel pair (2l, 2l+1) via half2 loads.
__global__ __launch_bounds__(256) void k_agg2(float* __restrict__ out,
                                              const float* __restrict__ b2, int n) {
    int node = blockIdx.x * 8 + (threadIdx.x >> 5);
    if (node >= n) return;
    int l = threadIdx.x & 31;
    bool act = (l < 20);
    int beg = g_rowptr[node], end = g_rowptr[node + 1];
    float dv = g_ald2[node];
    float aa = 0.f, ab = 0.f, psum = 0.f;
    int e = beg;
    for (; e + 2 <= end; e += 2) {
        int s0 = __ldg(&g_csrsrc[e]);
        int s1 = __ldg(&g_csrsrc[e + 1]);
        float v0 = __ldg(&g_als2[s0]);
        float v1 = __ldg(&g_als2[s1]);
        float2 f0 = make_float2(0.f, 0.f), f1 = make_float2(0.f, 0.f);
        if (act) {
            f0 = __half22float2(__ldg((const __half2*)(g_h2h + s0 * OUTC) + l));
            f1 = __half22float2(__ldg((const __half2*)(g_h2h + s1 * OUTC) + l));
        }
        float p0 = __expf(lrelu(v0 + dv));
        float p1 = __expf(lrelu(v1 + dv));
        aa += p0 * f0.x + p1 * f1.x;
        ab += p0 * f0.y + p1 * f1.y;
        psum += p0 + p1;
    }
    if (e < end) {
        int s0 = __ldg(&g_csrsrc[e]);
        float v0 = __ldg(&g_als2[s0]);
        float p0 = __expf(lrelu(v0 + dv));
        if (act) {
            float2 f0 = __half22float2(__ldg((const __half2*)(g_h2h + s0 * OUTC) + l));
            aa += p0 * f0.x;
            ab += p0 * f0.y;
        }
        psum += p0;
    }
    float inv = __fdividef(1.f, psum);
    float a = __int_as_float(0xff800000), b = __int_as_float(0xff800000);
    if (act) {
        float2 bb = *(const float2*)&b2[2 * l];
        a = aa * inv + bb.x;
        b = ab * inv + bb.y;
    }
    float mx = fmaxf(a, b);
#pragma unroll
    for (int o = 16; o; o >>= 1) mx = fmaxf(mx, __shfl_xor_sync(0xffffffffu, mx, o));
    float se = act ? (__expf(a - mx) + __expf(b - mx)) : 0.f;
#pragma unroll
    for (int o = 16; o; o >>= 1) se += __shfl_xor_sync(0xffffffffu, se, o);
    float lse = logf(se);
    if (act) {
        out[node * OUTC + 2 * l]     = a - mx - lse;
        out[node * OUTC + 2 * l + 1] = b - mx - lse;
    }
}

// ---------------- launch ----------------
static inline int cdiv(int a, int b) { return (a + b - 1) / b; }

extern "C" void kernel_launch(void* const* d_in, const int* in_sizes, int n_in,
                              void* d_out, int out_size) {
    const float* x      = (const float*)d_in[0];
    const int*   ei     = (const int*)  d_in[1];
    const float* W1     = (const float*)d_in[2];
    const float* a_src1 = (const float*)d_in[3];
    const float* a_dst1 = (const float*)d_in[4];
    const float* b1     = (const float*)d_in[5];
    const float* W2     = (const float*)d_in[6];
    const float* a_src2 = (const float*)d_in[7];
    const float* a_dst2 = (const float*)d_in[8];
    const float* b2     = (const float*)d_in[9];
    float* out = (float*)d_out;

    const int n  = NNODES;
    const int E  = in_sizes[1] / 2;
    const int nG1 = cdiv(n, 128);
    const int nS  = 592;
    const int nblk = cdiv(n, 256);

    const int prepW = D1 * INDIM + OUTC * D1 + n;
    k_prep <<<cdiv(prepW, 256), 256>>>(W1, W2, n);
    k_count<<<cdiv(E, 256), 256>>>(ei, E);
    k_scanA<<<nblk, 256>>>(n);
    k_scanB<<<1, 256>>>(nblk, n);
    k_scanC<<<nblk, 256>>>(n);
    k_g1s  <<<nG1 + nS, 256>>>(x, a_src1, a_dst1, ei, E, n, nG1, nS);
    k_agg1 <<<cdiv(n, 8), 256>>>(b1, n);
    k_gemm2<<<cdiv(n, 128), 256>>>(a_src2, a_dst2, n);
    k_agg2 <<<cdiv(n, 8), 256>>>(out, b2, n);
}